// round 6
// baseline (speedup 1.0000x reference)
#include <cuda_runtime.h>
#include <cuda_bf16.h>
#include <cstdint>

// ---------------- problem constants (fixed by dataset) ----------------
#define NNODES 100000
#define NEDGES 1600000
#define DH 128           // feature dim (D == H)
#define NG 512           // num graphs
#define NL 5             // total reps (input + 4 layers)
#define NLG 4            // GIN layers
#define OO 64            // output dim
#define BN_EPS 1e-5f

// ---------------- static device scratch (no allocations allowed) ------
__device__ float g_zl[NLG][(size_t)NNODES * DH];      // z per GIN layer
__device__ float g_pooled[(size_t)NNODES * DH];
__device__ float g_y1[(size_t)NNODES * DH];
__device__ int   g_deg[NNODES];
__device__ int   g_off[NNODES + 1];
__device__ int   g_cursor[NNODES];
__device__ int   g_srcs[NEDGES];
__device__ int   g_gstart[NG + 1];
__device__ int   g_bsum[128];
__device__ int   g_boff[129];
__device__ int   g_total;
__device__ float g_stats[NLG][2][2 * DH];   // [layer][stage][sum(128)|sumsq(128)]
__device__ float g_ph[NL][NG * DH];         // per-graph pooled reps
// bf16 hi/lo split weights, [n][k]: mats 0..3 = W1[l], 4..7 = W2[l]
__device__ __nv_bfloat16 g_whi[8][DH * DH];
__device__ __nv_bfloat16 g_wlo[8][DH * DH];

// ---------------- helpers ----------------------------------------------
__device__ __forceinline__ uint32_t smem_u32(const void* p) {
    uint32_t a;
    asm("{ .reg .u64 t; cvta.to.shared.u64 t, %1; cvt.u32.u64 %0, t; }"
        : "=r"(a) : "l"(p));
    return a;
}

__device__ __forceinline__ void ldx4(uint32_t* r, uint32_t addr) {
    asm volatile("ldmatrix.sync.aligned.m8n8.x4.shared.b16 {%0,%1,%2,%3}, [%4];"
                 : "=r"(r[0]), "=r"(r[1]), "=r"(r[2]), "=r"(r[3]) : "r"(addr));
}

__device__ __forceinline__ void mma16816(float* c, const uint32_t* a,
                                         uint32_t b0, uint32_t b1) {
    asm volatile(
        "mma.sync.aligned.m16n8k16.row.col.f32.bf16.bf16.f32 "
        "{%0,%1,%2,%3}, {%4,%5,%6,%7}, {%8,%9}, {%0,%1,%2,%3};"
        : "+f"(c[0]), "+f"(c[1]), "+f"(c[2]), "+f"(c[3])
        : "r"(a[0]), "r"(a[1]), "r"(a[2]), "r"(a[3]), "r"(b0), "r"(b1));
}

// smem tile geometry: rows x 136 bf16 (272B rows -> conflict-free ldmatrix)
#define LDT 136
#define OFF_AHI 0
#define OFF_ALO 17408                       // 64*136*2
#define OFF_BHI 34816
#define OFF_BLO 69632                       // +128*136*2
#define OFF_STATS 104448
#define SMEM_BYTES (104448 + 4 * 128 * 4)

// ---------------- small utility kernels --------------------------------
__global__ void zero_kernel(int n_nodes) {
    int i = blockIdx.x * blockDim.x + threadIdx.x;
    if (i < n_nodes) g_deg[i] = 0;
    if (i < NLG * 2 * 2 * DH) ((float*)g_stats)[i] = 0.0f;
}

__global__ void hist_kernel(const int* __restrict__ dst, int E) {
    int i = blockIdx.x * blockDim.x + threadIdx.x;
    if (i < E) atomicAdd(&g_deg[dst[i]], 1);
}

__global__ void scan1_kernel(int n) {
    __shared__ int warpsum[32];
    int tid = threadIdx.x, lane = tid & 31, wid = tid >> 5;
    int i = blockIdx.x * 1024 + tid;
    int v = (i < n) ? g_deg[i] : 0;
    int xv = v;
    #pragma unroll
    for (int o = 1; o < 32; o <<= 1) {
        int t = __shfl_up_sync(0xffffffffu, xv, o);
        if (lane >= o) xv += t;
    }
    if (lane == 31) warpsum[wid] = xv;
    __syncthreads();
    if (wid == 0) {
        int w = warpsum[lane];
        int yv = w;
        #pragma unroll
        for (int o = 1; o < 32; o <<= 1) {
            int t = __shfl_up_sync(0xffffffffu, yv, o);
            if (lane >= o) yv += t;
        }
        warpsum[lane] = yv - w;
    }
    __syncthreads();
    int excl = warpsum[wid] + xv - v;
    if (i < n) g_off[i] = excl;
    if (tid == 1023) g_bsum[blockIdx.x] = excl + v;
}

__global__ void scan2_kernel(int nb) {
    __shared__ int s[128];
    int tid = threadIdx.x;
    int v = (tid < nb) ? g_bsum[tid] : 0;
    s[tid] = v;
    __syncthreads();
    #pragma unroll
    for (int o = 1; o < 128; o <<= 1) {
        int t = (tid >= o) ? s[tid - o] : 0;
        __syncthreads();
        s[tid] += t;
        __syncthreads();
    }
    g_boff[tid] = s[tid] - v;
    if (tid == nb - 1) g_total = s[tid];
}

__global__ void scan3_kernel(int n) {
    int i = blockIdx.x * blockDim.x + threadIdx.x;
    if (i < n) {
        int o = g_off[i] + g_boff[i >> 10];
        g_off[i] = o;
        g_cursor[i] = o;
    }
    if (i == 0) g_off[n] = g_total;
}

__global__ void scatter_kernel(const int* __restrict__ src,
                               const int* __restrict__ dst, int E) {
    int i = blockIdx.x * blockDim.x + threadIdx.x;
    if (i < E) {
        int p = atomicAdd(&g_cursor[dst[i]], 1);
        g_srcs[p] = src[i];
    }
}

__global__ void gbounds_kernel(const int* __restrict__ gid, int n) {
    int i = blockIdx.x * blockDim.x + threadIdx.x;
    if (i > n) return;
    if (i == 0) {
        int b = gid[0];
        for (int g = 0; g <= b; ++g) g_gstart[g] = 0;
    } else if (i == n) {
        int a = gid[n - 1];
        for (int g = a + 1; g <= NG; ++g) g_gstart[g] = n;
    } else {
        int a = gid[i - 1], b = gid[i];
        for (int g = a + 1; g <= b; ++g) g_gstart[g] = i;
    }
}

// weight convert: W[k][n] fp32 -> [n][k] bf16 hi/lo (mats 0-3: W1, 4-7: W2)
__global__ void wconv_kernel(const float* __restrict__ W1,
                             const float* __restrict__ W2) {
    int i = blockIdx.x * blockDim.x + threadIdx.x;
    if (i >= 8 * DH * DH) return;
    int mat = i >> 14, r = i & 16383;
    int n = r >> 7, k = r & 127;
    const float* src = (mat < 4) ? (W1 + ((size_t)mat << 14))
                                 : (W2 + ((size_t)(mat - 4) << 14));
    float v = src[k * DH + n];
    __nv_bfloat16 hi = __float2bfloat16(v);
    __nv_bfloat16 lo = __float2bfloat16(v - __bfloat162float(hi));
    g_whi[mat][r] = hi;
    g_wlo[mat][r] = lo;
}

// ---------------- aggregation: warp per node, CSR gather ---------------
template <bool FIRST>
__global__ void agg_kernel(const float* __restrict__ Hsrc,
                           const float* __restrict__ go_prev,
                           const float* __restrict__ bo_prev,
                           const float* __restrict__ eps, int l, int n) {
    __shared__ float s_sc[128], s_sh[128];
    int tid = threadIdx.x;
    if (!FIRST) {
        if (tid < 128) {
            float inv = 1.0f / (float)n;
            float m = g_stats[l - 1][1][tid] * inv;
            float v = g_stats[l - 1][1][128 + tid] * inv - m * m;
            float s = __ldg(&go_prev[tid]) * rsqrtf(v + BN_EPS);
            s_sc[tid] = s;
            s_sh[tid] = __ldg(&bo_prev[tid]) - m * s;
        }
        __syncthreads();
    }
    int w = (blockIdx.x * blockDim.x + tid) >> 5;
    if (w >= n) return;
    int lane = tid & 31;
    float4 sc = make_float4(1.f, 1.f, 1.f, 1.f);
    float4 sh = make_float4(0.f, 0.f, 0.f, 0.f);
    if (!FIRST) {
        sc = *(float4*)&s_sc[lane * 4];
        sh = *(float4*)&s_sh[lane * 4];
    }
    float onepe = 1.0f + __ldg(&eps[l]);
    const float4* hv = (const float4*)Hsrc;

    float4 vs = __ldg(&hv[(size_t)w * 32 + lane]);
    float4 acc;
    if (!FIRST) {
        vs.x = fmaxf(fmaf(vs.x, sc.x, sh.x), 0.0f);
        vs.y = fmaxf(fmaf(vs.y, sc.y, sh.y), 0.0f);
        vs.z = fmaxf(fmaf(vs.z, sc.z, sh.z), 0.0f);
        vs.w = fmaxf(fmaf(vs.w, sc.w, sh.w), 0.0f);
    }
    acc.x = onepe * vs.x; acc.y = onepe * vs.y;
    acc.z = onepe * vs.z; acc.w = onepe * vs.w;

    int s = g_off[w], e = g_off[w + 1];
    int j = s;
    for (; j + 4 <= e; j += 4) {
        int s0 = g_srcs[j], s1 = g_srcs[j + 1], s2 = g_srcs[j + 2], s3 = g_srcs[j + 3];
        float4 v0 = __ldg(&hv[(size_t)s0 * 32 + lane]);
        float4 v1 = __ldg(&hv[(size_t)s1 * 32 + lane]);
        float4 v2 = __ldg(&hv[(size_t)s2 * 32 + lane]);
        float4 v3 = __ldg(&hv[(size_t)s3 * 32 + lane]);
        if (!FIRST) {
            v0.x = fmaxf(fmaf(v0.x, sc.x, sh.x), 0.0f);
            v0.y = fmaxf(fmaf(v0.y, sc.y, sh.y), 0.0f);
            v0.z = fmaxf(fmaf(v0.z, sc.z, sh.z), 0.0f);
            v0.w = fmaxf(fmaf(v0.w, sc.w, sh.w), 0.0f);
            v1.x = fmaxf(fmaf(v1.x, sc.x, sh.x), 0.0f);
            v1.y = fmaxf(fmaf(v1.y, sc.y, sh.y), 0.0f);
            v1.z = fmaxf(fmaf(v1.z, sc.z, sh.z), 0.0f);
            v1.w = fmaxf(fmaf(v1.w, sc.w, sh.w), 0.0f);
            v2.x = fmaxf(fmaf(v2.x, sc.x, sh.x), 0.0f);
            v2.y = fmaxf(fmaf(v2.y, sc.y, sh.y), 0.0f);
            v2.z = fmaxf(fmaf(v2.z, sc.z, sh.z), 0.0f);
            v2.w = fmaxf(fmaf(v2.w, sc.w, sh.w), 0.0f);
            v3.x = fmaxf(fmaf(v3.x, sc.x, sh.x), 0.0f);
            v3.y = fmaxf(fmaf(v3.y, sc.y, sh.y), 0.0f);
            v3.z = fmaxf(fmaf(v3.z, sc.z, sh.z), 0.0f);
            v3.w = fmaxf(fmaf(v3.w, sc.w, sh.w), 0.0f);
        }
        acc.x += (v0.x + v1.x) + (v2.x + v3.x);
        acc.y += (v0.y + v1.y) + (v2.y + v3.y);
        acc.z += (v0.z + v1.z) + (v2.z + v3.z);
        acc.w += (v0.w + v1.w) + (v2.w + v3.w);
    }
    for (; j < e; ++j) {
        float4 v0 = __ldg(&hv[(size_t)g_srcs[j] * 32 + lane]);
        if (!FIRST) {
            v0.x = fmaxf(fmaf(v0.x, sc.x, sh.x), 0.0f);
            v0.y = fmaxf(fmaf(v0.y, sc.y, sh.y), 0.0f);
            v0.z = fmaxf(fmaf(v0.z, sc.z, sh.z), 0.0f);
            v0.w = fmaxf(fmaf(v0.w, sc.w, sh.w), 0.0f);
        }
        acc.x += v0.x; acc.y += v0.y; acc.z += v0.z; acc.w += v0.w;
    }
    ((float4*)g_pooled)[(size_t)w * 32 + lane] = acc;
}

// ---------------- bf16-split mma GEMM, 64-row tiles, 2 CTAs/SM ---------
// C[M,128] = f(A)[M,128] @ Wt^T + bias ; f = identity or relu(bn(stage0)).
// Accumulates column sum/sumsq into g_stats[l][stage].
template <bool PRE_BN>
__global__ void __launch_bounds__(256, 2)
gemm_mma64(const float* __restrict__ A,
           const __nv_bfloat16* __restrict__ Bhi,
           const __nv_bfloat16* __restrict__ Blo,
           const float* __restrict__ bias,
           const float* __restrict__ gamma, const float* __restrict__ beta,
           float* __restrict__ C, int l, int M) {
    extern __shared__ char sb[];
    __nv_bfloat16* sAhi = (__nv_bfloat16*)(sb + OFF_AHI);
    __nv_bfloat16* sAlo = (__nv_bfloat16*)(sb + OFF_ALO);
    __nv_bfloat16* sBhi = (__nv_bfloat16*)(sb + OFF_BHI);
    __nv_bfloat16* sBlo = (__nv_bfloat16*)(sb + OFF_BLO);
    float* s_scale = (float*)(sb + OFF_STATS);
    float* s_shift = s_scale + 128;
    float* s_sum   = s_shift + 128;
    float* s_sq    = s_sum + 128;

    int tid = threadIdx.x;
    if (tid < 128) { s_sum[tid] = 0.0f; s_sq[tid] = 0.0f; }
    if (PRE_BN && tid < 128) {
        float inv = 1.0f / (float)M;
        float m = g_stats[l][0][tid] * inv;
        float v = g_stats[l][0][128 + tid] * inv - m * m;
        float s = __ldg(&gamma[tid]) * rsqrtf(v + BN_EPS);
        s_scale[tid] = s;
        s_shift[tid] = __ldg(&beta[tid]) - m * s;
    }

    // ---- stage B hi/lo ([n][k] bf16) into smem ----
    const uint32_t* bh = (const uint32_t*)Bhi;
    const uint32_t* bl = (const uint32_t*)Blo;
    #pragma unroll
    for (int it = 0; it < 32; ++it) {
        int i = tid + it * 256;              // 8192 u32
        int n = i >> 6, kp = i & 63;
        int d = n * LDT + kp * 2;
        *(uint32_t*)&sBhi[d] = bh[i];
        *(uint32_t*)&sBlo[d] = bl[i];
    }
    __syncthreads();   // scale/shift + B ready

    // ---- stage A tile (64 rows fp32 -> optional BN/ReLU -> bf16 hi/lo) ----
    int row0 = blockIdx.x * 64;
    const float4* A4 = (const float4*)(A + (size_t)row0 * DH);
    #pragma unroll
    for (int it = 0; it < 8; ++it) {
        int idx = tid + it * 256;            // 2048 float4
        int r = idx >> 5, c4 = (idx & 31) * 4;
        float4 v = make_float4(0.f, 0.f, 0.f, 0.f);
        if (row0 + r < M) v = A4[idx];
        if (PRE_BN) {
            v.x = fmaxf(fmaf(v.x, s_scale[c4 + 0], s_shift[c4 + 0]), 0.0f);
            v.y = fmaxf(fmaf(v.y, s_scale[c4 + 1], s_shift[c4 + 1]), 0.0f);
            v.z = fmaxf(fmaf(v.z, s_scale[c4 + 2], s_shift[c4 + 2]), 0.0f);
            v.w = fmaxf(fmaf(v.w, s_scale[c4 + 3], s_shift[c4 + 3]), 0.0f);
        }
        __nv_bfloat16 hx = __float2bfloat16(v.x), hy = __float2bfloat16(v.y);
        __nv_bfloat16 hz = __float2bfloat16(v.z), hw = __float2bfloat16(v.w);
        uint2 hi2, lo2;
        {
            __nv_bfloat162 t01, t23;
            t01.x = hx; t01.y = hy; t23.x = hz; t23.y = hw;
            hi2.x = *(uint32_t*)&t01; hi2.y = *(uint32_t*)&t23;
            t01.x = __float2bfloat16(v.x - __bfloat162float(hx));
            t01.y = __float2bfloat16(v.y - __bfloat162float(hy));
            t23.x = __float2bfloat16(v.z - __bfloat162float(hz));
            t23.y = __float2bfloat16(v.w - __bfloat162float(hw));
            lo2.x = *(uint32_t*)&t01; lo2.y = *(uint32_t*)&t23;
        }
        int d = r * LDT + c4;
        *(uint2*)&sAhi[d] = hi2;
        *(uint2*)&sAlo[d] = lo2;
    }
    __syncthreads();

    // ---- warp-tile mma: 2(m) x 4(n) warps, each 32x32 ----
    int w = tid >> 5, lane = tid & 31;
    int mw = (w >> 2) * 32, nw = (w & 3) * 32;
    uint32_t base = smem_u32(sb);
    uint32_t aoff = ((mw + (lane & 15)) * LDT + ((lane >> 4) * 8)) * 2;
    uint32_t boff = ((nw + (lane & 7) + ((lane >> 4) << 3)) * LDT
                     + (((lane >> 3) & 1) * 8)) * 2;

    float acc[2][4][4];
    #pragma unroll
    for (int i = 0; i < 2; ++i)
        #pragma unroll
        for (int j = 0; j < 4; ++j)
            #pragma unroll
            for (int k = 0; k < 4; ++k) acc[i][j][k] = 0.0f;

    const uint32_t aT[3] = {OFF_AHI, OFF_ALO, OFF_AHI};
    const uint32_t bT[3] = {OFF_BHI, OFF_BHI, OFF_BLO};
    #pragma unroll
    for (int t = 0; t < 3; ++t) {
        uint32_t ab = base + aT[t] + aoff;
        uint32_t bb = base + bT[t] + boff;
        #pragma unroll
        for (int ks = 0; ks < 8; ++ks) {
            uint32_t a0[4], a1[4], b0[4], b1[4];
            ldx4(a0, ab + ks * 32);
            ldx4(a1, ab + 16 * LDT * 2 + ks * 32);
            ldx4(b0, bb + ks * 32);
            ldx4(b1, bb + 16 * LDT * 2 + ks * 32);
            mma16816(acc[0][0], a0, b0[0], b0[1]);
            mma16816(acc[0][1], a0, b0[2], b0[3]);
            mma16816(acc[0][2], a0, b1[0], b1[1]);
            mma16816(acc[0][3], a0, b1[2], b1[3]);
            mma16816(acc[1][0], a1, b0[0], b0[1]);
            mma16816(acc[1][1], a1, b0[2], b0[3]);
            mma16816(acc[1][2], a1, b1[0], b1[1]);
            mma16816(acc[1][3], a1, b1[2], b1[3]);
        }
    }

    // ---- epilogue: bias, direct store, column stats ----
    float csum[8], csq[8];
    #pragma unroll
    for (int i = 0; i < 8; ++i) { csum[i] = 0.0f; csq[i] = 0.0f; }
    #pragma unroll
    for (int nf = 0; nf < 4; ++nf) {
        int col = nw + nf * 8 + (lane & 3) * 2;
        float bx = __ldg(&bias[col]), by = __ldg(&bias[col + 1]);
        #pragma unroll
        for (int mf = 0; mf < 2; ++mf) {
            int r0 = row0 + mw + mf * 16 + (lane >> 2);
            float v0 = acc[mf][nf][0] + bx, v1 = acc[mf][nf][1] + by;
            float v2 = acc[mf][nf][2] + bx, v3 = acc[mf][nf][3] + by;
            if (r0 < M) {
                *(float2*)&C[(size_t)r0 * DH + col] = make_float2(v0, v1);
                csum[nf * 2] += v0; csum[nf * 2 + 1] += v1;
                csq[nf * 2] += v0 * v0; csq[nf * 2 + 1] += v1 * v1;
            }
            if (r0 + 8 < M) {
                *(float2*)&C[(size_t)(r0 + 8) * DH + col] = make_float2(v2, v3);
                csum[nf * 2] += v2; csum[nf * 2 + 1] += v3;
                csq[nf * 2] += v2 * v2; csq[nf * 2 + 1] += v3 * v3;
            }
        }
    }
    #pragma unroll
    for (int nf = 0; nf < 4; ++nf) {
        int col = nw + nf * 8 + (lane & 3) * 2;
        atomicAdd(&s_sum[col], csum[nf * 2]);
        atomicAdd(&s_sum[col + 1], csum[nf * 2 + 1]);
        atomicAdd(&s_sq[col], csq[nf * 2]);
        atomicAdd(&s_sq[col + 1], csq[nf * 2 + 1]);
    }
    __syncthreads();
    const int stage = PRE_BN ? 1 : 0;
    if (tid < 128) {
        atomicAdd(&g_stats[l][stage][tid], s_sum[tid]);
        atomicAdd(&g_stats[l][stage][128 + tid], s_sq[tid]);
    }
}

// ---------------- per-graph pooling (applies BN+ReLU on the fly) -------
__global__ void pool_kernel(const float* __restrict__ x,
                            const float* __restrict__ go,
                            const float* __restrict__ bo, int M) {
    int g = blockIdx.x, lp = blockIdx.y, c = threadIdx.x;
    int s = g_gstart[g], e = g_gstart[g + 1];
    float acc = 0.0f;
    if (lp == 0) {
        const float* h = x;
        for (int r = s; r < e; ++r) acc += __ldg(&h[(size_t)r * DH + c]);
    } else {
        int l = lp - 1;
        const float* z = &g_zl[l][0];
        float inv = 1.0f / (float)M;
        float m = g_stats[l][1][c] * inv;
        float v = g_stats[l][1][128 + c] * inv - m * m;
        float scl = __ldg(&go[l * DH + c]) * rsqrtf(v + BN_EPS);
        float shf = __ldg(&bo[l * DH + c]) - m * scl;
        for (int r = s; r < e; ++r)
            acc += fmaxf(fmaf(__ldg(&z[(size_t)r * DH + c]), scl, shf), 0.0f);
    }
    g_ph[lp][g * DH + c] = acc;
}

// ---------------- final score: 512 x 64 --------------------------------
__global__ void score_kernel(const float* __restrict__ Wp,
                             const float* __restrict__ bp,
                             float* __restrict__ out) {
    int g = blockIdx.x;
    __shared__ float sph[NL * DH];
    for (int i = threadIdx.x; i < NL * DH; i += blockDim.x) {
        int l = i / DH, c = i % DH;
        sph[i] = g_ph[l][g * DH + c];
    }
    __syncthreads();
    int o = threadIdx.x;  // 64 threads
    float acc = 0.0f;
    for (int l = 0; l < NL; ++l) {
        acc += __ldg(&bp[l * OO + o]);
        const float* Wl = Wp + (size_t)l * DH * OO;
        #pragma unroll 4
        for (int c = 0; c < DH; ++c)
            acc = fmaf(sph[l * DH + c], __ldg(&Wl[c * OO + o]), acc);
    }
    out[g * OO + o] = acc;
}

// ---------------- launcher ---------------------------------------------
extern "C" void kernel_launch(void* const* d_in, const int* in_sizes, int n_in,
                              void* d_out, int out_size) {
    const float* x   = (const float*)d_in[0];
    const int*   src = (const int*)d_in[1];
    const int*   dst = (const int*)d_in[2];
    const int*   gid = (const int*)d_in[3];
    const float* eps = (const float*)d_in[5];
    const float* W1  = (const float*)d_in[6];
    const float* b1  = (const float*)d_in[7];
    const float* gm  = (const float*)d_in[8];
    const float* bm  = (const float*)d_in[9];
    const float* W2  = (const float*)d_in[10];
    const float* b2  = (const float*)d_in[11];
    const float* go  = (const float*)d_in[12];
    const float* bo  = (const float*)d_in[13];
    const float* Wp  = (const float*)d_in[14];
    const float* bp  = (const float*)d_in[15];
    float* out = (float*)d_out;

    int N = in_sizes[0] / DH;   // 100000
    int E = in_sizes[1];        // 1600000

    float *pooled, *y1, *zl;
    __nv_bfloat16 *whi, *wlo;
    cudaGetSymbolAddress((void**)&pooled, g_pooled);
    cudaGetSymbolAddress((void**)&y1, g_y1);
    cudaGetSymbolAddress((void**)&zl, g_zl);
    cudaGetSymbolAddress((void**)&whi, g_whi);
    cudaGetSymbolAddress((void**)&wlo, g_wlo);

    static bool attr_done = false;
    if (!attr_done) {
        cudaFuncSetAttribute(gemm_mma64<false>,
                             cudaFuncAttributeMaxDynamicSharedMemorySize, SMEM_BYTES);
        cudaFuncSetAttribute(gemm_mma64<true>,
                             cudaFuncAttributeMaxDynamicSharedMemorySize, SMEM_BYTES);
        attr_done = true;
    }

    int nb = (N + 1023) / 1024;

    zero_kernel<<<(N + 255) / 256, 256>>>(N);
    hist_kernel<<<(E + 255) / 256, 256>>>(dst, E);
    scan1_kernel<<<nb, 1024>>>(N);
    scan2_kernel<<<1, 128>>>(nb);
    scan3_kernel<<<(N + 255) / 256, 256>>>(N);
    scatter_kernel<<<(E + 255) / 256, 256>>>(src, dst, E);
    gbounds_kernel<<<(N + 1 + 255) / 256, 256>>>(gid, N);
    wconv_kernel<<<(8 * DH * DH + 255) / 256, 256>>>(W1, W2);

    int gemmGrid = (N + 63) / 64;
    int aggGrid  = (N * 32 + 255) / 256;  // warp per node

    for (int l = 0; l < NLG; ++l) {
        float* z_out = zl + (size_t)l * (size_t)NNODES * DH;
        if (l == 0) {
            agg_kernel<true><<<aggGrid, 256>>>(x, nullptr, nullptr, eps, l, N);
        } else {
            const float* zprev = zl + (size_t)(l - 1) * (size_t)NNODES * DH;
            agg_kernel<false><<<aggGrid, 256>>>(zprev, go + (l - 1) * DH,
                                                bo + (l - 1) * DH, eps, l, N);
        }
        gemm_mma64<false><<<gemmGrid, 256, SMEM_BYTES>>>(
            pooled, whi + (size_t)l * DH * DH, wlo + (size_t)l * DH * DH,
            b1 + l * DH, nullptr, nullptr, y1, l, N);
        gemm_mma64<true><<<gemmGrid, 256, SMEM_BYTES>>>(
            y1, whi + (size_t)(4 + l) * DH * DH, wlo + (size_t)(4 + l) * DH * DH,
            b2 + l * DH, gm + l * DH, bm + l * DH, z_out, l, N);
    }

    dim3 pg(NG, NL);
    pool_kernel<<<pg, DH>>>(x, go, bo, N);
    score_kernel<<<NG, 64>>>(Wp, bp, out);
}

// round 7
// speedup vs baseline: 1.0188x; 1.0188x over previous
#include <cuda_runtime.h>
#include <cuda_fp16.h>
#include <cstdint>

// ---------------- problem constants (fixed by dataset) ----------------
#define NNODES 100000
#define NEDGES 1600000
#define DH 128           // feature dim (D == H)
#define NG 512           // num graphs
#define NL 5             // total reps (input + 4 layers)
#define NLG 4            // GIN layers
#define OO 64            // output dim
#define BN_EPS 1e-5f

// ---------------- static device scratch (no allocations allowed) ------
__device__ __half g_h16[NL][(size_t)NNODES * DH];  // slot0=x16, slot l+1=h_l
__device__ float g_z[(size_t)NNODES * DH];
__device__ float g_pooled[(size_t)NNODES * DH];
__device__ float g_y1[(size_t)NNODES * DH];
__device__ int   g_deg[NNODES];
__device__ int   g_off[NNODES + 1];
__device__ int   g_cursor[NNODES];
__device__ int   g_srcs[NEDGES];
__device__ int   g_gstart[NG + 1];
__device__ int   g_bsum[128];
__device__ int   g_boff[129];
__device__ int   g_total;
__device__ float g_stats[NLG][2][2 * DH];   // [layer][stage][sum|sumsq]
__device__ float g_ph[NL][NG * DH];         // per-graph pooled reps

// ---------------- small utility kernels --------------------------------
__global__ void zero_kernel(int n_nodes) {
    int i = blockIdx.x * blockDim.x + threadIdx.x;
    if (i < n_nodes) g_deg[i] = 0;
    if (i < NLG * 2 * 2 * DH) ((float*)g_stats)[i] = 0.0f;
}

__global__ void hist_kernel(const int* __restrict__ dst, int E) {
    int i = blockIdx.x * blockDim.x + threadIdx.x;
    if (i < E) atomicAdd(&g_deg[dst[i]], 1);
}

__global__ void scan1_kernel(int n) {
    __shared__ int warpsum[32];
    int tid = threadIdx.x, lane = tid & 31, wid = tid >> 5;
    int i = blockIdx.x * 1024 + tid;
    int v = (i < n) ? g_deg[i] : 0;
    int xv = v;
    #pragma unroll
    for (int o = 1; o < 32; o <<= 1) {
        int t = __shfl_up_sync(0xffffffffu, xv, o);
        if (lane >= o) xv += t;
    }
    if (lane == 31) warpsum[wid] = xv;
    __syncthreads();
    if (wid == 0) {
        int w = warpsum[lane];
        int yv = w;
        #pragma unroll
        for (int o = 1; o < 32; o <<= 1) {
            int t = __shfl_up_sync(0xffffffffu, yv, o);
            if (lane >= o) yv += t;
        }
        warpsum[lane] = yv - w;
    }
    __syncthreads();
    int excl = warpsum[wid] + xv - v;
    if (i < n) g_off[i] = excl;
    if (tid == 1023) g_bsum[blockIdx.x] = excl + v;
}

__global__ void scan2_kernel(int nb) {
    __shared__ int s[128];
    int tid = threadIdx.x;
    int v = (tid < nb) ? g_bsum[tid] : 0;
    s[tid] = v;
    __syncthreads();
    #pragma unroll
    for (int o = 1; o < 128; o <<= 1) {
        int t = (tid >= o) ? s[tid - o] : 0;
        __syncthreads();
        s[tid] += t;
        __syncthreads();
    }
    g_boff[tid] = s[tid] - v;
    if (tid == nb - 1) g_total = s[tid];
}

__global__ void scan3_kernel(int n) {
    int i = blockIdx.x * blockDim.x + threadIdx.x;
    if (i < n) {
        int o = g_off[i] + g_boff[i >> 10];
        g_off[i] = o;
        g_cursor[i] = o;
    }
    if (i == 0) g_off[n] = g_total;
}

__global__ void scatter_kernel(const int* __restrict__ src,
                               const int* __restrict__ dst, int E) {
    int i = blockIdx.x * blockDim.x + threadIdx.x;
    if (i < E) {
        int p = atomicAdd(&g_cursor[dst[i]], 1);
        g_srcs[p] = src[i];
    }
}

__global__ void gbounds_kernel(const int* __restrict__ gid, int n) {
    int i = blockIdx.x * blockDim.x + threadIdx.x;
    if (i > n) return;
    if (i == 0) {
        int b = gid[0];
        for (int g = 0; g <= b; ++g) g_gstart[g] = 0;
    } else if (i == n) {
        int a = gid[n - 1];
        for (int g = a + 1; g <= NG; ++g) g_gstart[g] = n;
    } else {
        int a = gid[i - 1], b = gid[i];
        for (int g = a + 1; g <= b; ++g) g_gstart[g] = i;
    }
}

// x -> fp16 copy (slot 0)
__global__ void xconv_kernel(const float* __restrict__ x, int M) {
    int idx = blockIdx.x * blockDim.x + threadIdx.x;  // float4 index
    if (idx >= M * 32) return;
    float4 v = ((const float4*)x)[idx];
    __half2 a = __floats2half2_rn(v.x, v.y);
    __half2 b = __floats2half2_rn(v.z, v.w);
    uint2 u;
    u.x = *(uint32_t*)&a; u.y = *(uint32_t*)&b;
    ((uint2*)&g_h16[0][0])[idx] = u;
}

// h16[l+1] = fp16(relu(bn_outer(z))) using stage-1 stats
__global__ void hconv_kernel(const float* __restrict__ z,
                             const float* __restrict__ go,
                             const float* __restrict__ bo, int l, int M) {
    __shared__ float s_scale[128], s_shift[128];
    int tid = threadIdx.x;
    if (tid < 128) {
        float inv = 1.0f / (float)M;
        float m = g_stats[l][1][tid] * inv;
        float v = g_stats[l][1][128 + tid] * inv - m * m;
        float s = __ldg(&go[tid]) * rsqrtf(v + BN_EPS);
        s_scale[tid] = s;
        s_shift[tid] = __ldg(&bo[tid]) - m * s;
    }
    __syncthreads();
    int idx = blockIdx.x * blockDim.x + tid;  // float4 index
    if (idx >= M * 32) return;
    int c = (idx & 31) * 4;
    float4 v = ((const float4*)z)[idx];
    float o0 = fmaxf(fmaf(v.x, s_scale[c + 0], s_shift[c + 0]), 0.0f);
    float o1 = fmaxf(fmaf(v.y, s_scale[c + 1], s_shift[c + 1]), 0.0f);
    float o2 = fmaxf(fmaf(v.z, s_scale[c + 2], s_shift[c + 2]), 0.0f);
    float o3 = fmaxf(fmaf(v.w, s_scale[c + 3], s_shift[c + 3]), 0.0f);
    __half2 a = __floats2half2_rn(o0, o1);
    __half2 b = __floats2half2_rn(o2, o3);
    uint2 u;
    u.x = *(uint32_t*)&a; u.y = *(uint32_t*)&b;
    ((uint2*)&g_h16[l + 1][0])[idx] = u;
}

// ---------------- aggregation: warp per node, fp16 CSR gather ----------
__global__ void agg_kernel(const __half* __restrict__ H16,
                           const float* __restrict__ eps, int l, int n) {
    int w = (blockIdx.x * blockDim.x + threadIdx.x) >> 5;
    if (w >= n) return;
    int lane = threadIdx.x & 31;
    float onepe = 1.0f + __ldg(&eps[l]);
    const uint2* hv = (const uint2*)H16;   // 32 uint2 (8B) per 256B row

    uint2 su = __ldg(&hv[(size_t)w * 32 + lane]);
    float2 f0 = __half22float2(*(__half2*)&su.x);
    float2 f1 = __half22float2(*(__half2*)&su.y);
    float4 acc = make_float4(onepe * f0.x, onepe * f0.y,
                             onepe * f1.x, onepe * f1.y);

    int s = g_off[w], e = g_off[w + 1];
    int j = s;
    for (; j + 4 <= e; j += 4) {
        int s0 = g_srcs[j], s1 = g_srcs[j + 1], s2 = g_srcs[j + 2], s3 = g_srcs[j + 3];
        uint2 u0 = __ldg(&hv[(size_t)s0 * 32 + lane]);
        uint2 u1 = __ldg(&hv[(size_t)s1 * 32 + lane]);
        uint2 u2 = __ldg(&hv[(size_t)s2 * 32 + lane]);
        uint2 u3 = __ldg(&hv[(size_t)s3 * 32 + lane]);
        float2 a0 = __half22float2(*(__half2*)&u0.x), b0 = __half22float2(*(__half2*)&u0.y);
        float2 a1 = __half22float2(*(__half2*)&u1.x), b1 = __half22float2(*(__half2*)&u1.y);
        float2 a2 = __half22float2(*(__half2*)&u2.x), b2 = __half22float2(*(__half2*)&u2.y);
        float2 a3 = __half22float2(*(__half2*)&u3.x), b3 = __half22float2(*(__half2*)&u3.y);
        acc.x += (a0.x + a1.x) + (a2.x + a3.x);
        acc.y += (a0.y + a1.y) + (a2.y + a3.y);
        acc.z += (b0.x + b1.x) + (b2.x + b3.x);
        acc.w += (b0.y + b1.y) + (b2.y + b3.y);
    }
    for (; j < e; ++j) {
        uint2 u0 = __ldg(&hv[(size_t)g_srcs[j] * 32 + lane]);
        float2 a0 = __half22float2(*(__half2*)&u0.x);
        float2 b0 = __half22float2(*(__half2*)&u0.y);
        acc.x += a0.x; acc.y += a0.y; acc.z += b0.x; acc.w += b0.y;
    }
    ((float4*)g_pooled)[(size_t)w * 32 + lane] = acc;
}

// ---------------- fused GEMM (+optional pre-BN/ReLU on A, +col stats) --
// C[M,128] = f(A)[M,128] @ W[128,128] + bias ; accumulate col sum/sumsq
template <bool PRE_BN>
__global__ void __launch_bounds__(256, 2)
gemm_kernel(const float* __restrict__ A, const float* __restrict__ W,
            const float* __restrict__ bias,
            const float* __restrict__ gamma, const float* __restrict__ beta,
            float* __restrict__ C, int l, int M) {
    __shared__ float As[8][132];
    __shared__ float Ws[8][128];
    __shared__ float s_scale[128], s_shift[128];
    __shared__ float s_sum[128], s_sq[128];
    int tid = threadIdx.x;
    if (PRE_BN) {
        if (tid < 128) {
            float inv = 1.0f / (float)M;
            float su = g_stats[l][0][tid], sq = g_stats[l][0][128 + tid];
            float m = su * inv;
            float v = sq * inv - m * m;
            float s = __ldg(&gamma[tid]) * rsqrtf(v + BN_EPS);
            s_scale[tid] = s;
            s_shift[tid] = __ldg(&beta[tid]) - m * s;
        }
    }
    if (tid < 128) { s_sum[tid] = 0.0f; s_sq[tid] = 0.0f; }
    __syncthreads();

    int row0 = blockIdx.x * 128;
    int tx = tid & 15, ty = tid >> 4;
    int arow = tid >> 1, acol = (tid & 1) * 4;
    int wrow = tid >> 5, wcol = (tid & 31) * 4;
    int grow = row0 + arow;
    bool aval = (grow < M);
    const float* Aptr = A + (size_t)grow * 128 + acol;
    const float* Wptr = W + (size_t)wrow * 128 + wcol;

    float acc[8][8];
    #pragma unroll
    for (int i = 0; i < 8; ++i)
        #pragma unroll
        for (int j = 0; j < 8; ++j) acc[i][j] = 0.0f;

    for (int kb = 0; kb < 128; kb += 8) {
        float4 av = aval ? *(const float4*)(Aptr + kb) : make_float4(0, 0, 0, 0);
        float4 wv = *(const float4*)(Wptr + (size_t)kb * 128);
        if (PRE_BN && aval) {
            int c = kb + acol;
            av.x = fmaxf(fmaf(av.x, s_scale[c + 0], s_shift[c + 0]), 0.0f);
            av.y = fmaxf(fmaf(av.y, s_scale[c + 1], s_shift[c + 1]), 0.0f);
            av.z = fmaxf(fmaf(av.z, s_scale[c + 2], s_shift[c + 2]), 0.0f);
            av.w = fmaxf(fmaf(av.w, s_scale[c + 3], s_shift[c + 3]), 0.0f);
        }
        __syncthreads();
        As[acol + 0][arow] = av.x;
        As[acol + 1][arow] = av.y;
        As[acol + 2][arow] = av.z;
        As[acol + 3][arow] = av.w;
        *(float4*)&Ws[wrow][wcol] = wv;
        __syncthreads();
        #pragma unroll
        for (int k = 0; k < 8; ++k) {
            float a[8], b[8];
            *(float4*)&a[0] = *(const float4*)&As[k][ty * 8];
            *(float4*)&a[4] = *(const float4*)&As[k][ty * 8 + 4];
            *(float4*)&b[0] = *(const float4*)&Ws[k][tx * 8];
            *(float4*)&b[4] = *(const float4*)&Ws[k][tx * 8 + 4];
            #pragma unroll
            for (int i = 0; i < 8; ++i)
                #pragma unroll
                for (int j = 0; j < 8; ++j)
                    acc[i][j] = fmaf(a[i], b[j], acc[i][j]);
        }
    }

    float bcol[8];
    #pragma unroll
    for (int j = 0; j < 8; ++j) bcol[j] = __ldg(&bias[tx * 8 + j]);
    float psum[8], psq[8];
    #pragma unroll
    for (int j = 0; j < 8; ++j) { psum[j] = 0.0f; psq[j] = 0.0f; }
    #pragma unroll
    for (int i = 0; i < 8; ++i) {
        int gr = row0 + ty * 8 + i;
        if (gr < M) {
            float v[8];
            #pragma unroll
            for (int j = 0; j < 8; ++j) {
                v[j] = acc[i][j] + bcol[j];
                psum[j] += v[j];
                psq[j]  += v[j] * v[j];
            }
            float4 o0 = make_float4(v[0], v[1], v[2], v[3]);
            float4 o1 = make_float4(v[4], v[5], v[6], v[7]);
            *(float4*)&C[(size_t)gr * 128 + tx * 8]     = o0;
            *(float4*)&C[(size_t)gr * 128 + tx * 8 + 4] = o1;
        }
    }
    #pragma unroll
    for (int j = 0; j < 8; ++j) {
        atomicAdd(&s_sum[tx * 8 + j], psum[j]);
        atomicAdd(&s_sq[tx * 8 + j], psq[j]);
    }
    __syncthreads();
    const int stage = PRE_BN ? 1 : 0;
    if (tid < 128) {
        atomicAdd(&g_stats[l][stage][tid], s_sum[tid]);
        atomicAdd(&g_stats[l][stage][128 + tid], s_sq[tid]);
    }
}

// ---------------- per-graph pooling over fp16 reps ---------------------
__global__ void pool_kernel() {
    int g = blockIdx.x, lp = blockIdx.y, c = threadIdx.x;   // 128 threads
    int s = g_gstart[g], e = g_gstart[g + 1];
    const __half* h = &g_h16[lp][0];
    float acc = 0.0f;
    int r = s;
    for (; r + 4 <= e; r += 4) {
        acc += __half2float(__ldg(&h[(size_t)(r + 0) * DH + c]));
        acc += __half2float(__ldg(&h[(size_t)(r + 1) * DH + c]));
        acc += __half2float(__ldg(&h[(size_t)(r + 2) * DH + c]));
        acc += __half2float(__ldg(&h[(size_t)(r + 3) * DH + c]));
    }
    for (; r < e; ++r)
        acc += __half2float(__ldg(&h[(size_t)r * DH + c]));
    g_ph[lp][g * DH + c] = acc;
}

// ---------------- final score: 512 x 64 --------------------------------
__global__ void score_kernel(const float* __restrict__ Wp,
                             const float* __restrict__ bp,
                             float* __restrict__ out) {
    int g = blockIdx.x;
    __shared__ float sph[NL * DH];
    for (int i = threadIdx.x; i < NL * DH; i += blockDim.x) {
        int l = i / DH, c = i % DH;
        sph[i] = g_ph[l][g * DH + c];
    }
    __syncthreads();
    int o = threadIdx.x;  // 64 threads
    float acc = 0.0f;
    for (int l = 0; l < NL; ++l) {
        acc += __ldg(&bp[l * OO + o]);
        const float* Wl = Wp + (size_t)l * DH * OO;
        #pragma unroll 4
        for (int c = 0; c < DH; ++c)
            acc = fmaf(sph[l * DH + c], __ldg(&Wl[c * OO + o]), acc);
    }
    out[g * OO + o] = acc;
}

// ---------------- launcher ---------------------------------------------
extern "C" void kernel_launch(void* const* d_in, const int* in_sizes, int n_in,
                              void* d_out, int out_size) {
    const float* x   = (const float*)d_in[0];
    const int*   src = (const int*)d_in[1];
    const int*   dst = (const int*)d_in[2];
    const int*   gid = (const int*)d_in[3];
    const float* eps = (const float*)d_in[5];
    const float* W1  = (const float*)d_in[6];
    const float* b1  = (const float*)d_in[7];
    const float* gm  = (const float*)d_in[8];
    const float* bm  = (const float*)d_in[9];
    const float* W2  = (const float*)d_in[10];
    const float* b2  = (const float*)d_in[11];
    const float* go  = (const float*)d_in[12];
    const float* bo  = (const float*)d_in[13];
    const float* Wp  = (const float*)d_in[14];
    const float* bp  = (const float*)d_in[15];
    float* out = (float*)d_out;

    int N = in_sizes[0] / DH;   // 100000
    int E = in_sizes[1];        // 1600000

    float *pooled, *y1, *z;
    __half *h16;
    cudaGetSymbolAddress((void**)&pooled, g_pooled);
    cudaGetSymbolAddress((void**)&y1, g_y1);
    cudaGetSymbolAddress((void**)&z, g_z);
    cudaGetSymbolAddress((void**)&h16, g_h16);

    int nb = (N + 1023) / 1024;
    int elemGrid = (N * 32 + 255) / 256;

    zero_kernel<<<(N + 255) / 256, 256>>>(N);
    hist_kernel<<<(E + 255) / 256, 256>>>(dst, E);
    scan1_kernel<<<nb, 1024>>>(N);
    scan2_kernel<<<1, 128>>>(nb);
    scan3_kernel<<<(N + 255) / 256, 256>>>(N);
    scatter_kernel<<<(E + 255) / 256, 256>>>(src, dst, E);
    gbounds_kernel<<<(N + 1 + 255) / 256, 256>>>(gid, N);
    xconv_kernel<<<elemGrid, 256>>>(x, N);

    int gemmGrid = (N + 127) / 128;
    int aggGrid  = (N * 32 + 255) / 256;  // warp per node

    for (int l = 0; l < NLG; ++l) {
        const __half* hin = h16 + (size_t)l * (size_t)NNODES * DH;
        agg_kernel<<<aggGrid, 256>>>(hin, eps, l, N);
        gemm_kernel<false><<<gemmGrid, 256>>>(pooled, W1 + (size_t)l * DH * DH,
                                              b1 + l * DH, nullptr, nullptr,
                                              y1, l, N);
        gemm_kernel<true><<<gemmGrid, 256>>>(y1, W2 + (size_t)l * DH * DH,
                                             b2 + l * DH, gm + l * DH, bm + l * DH,
                                             z, l, N);
        hconv_kernel<<<elemGrid, 256>>>(z, go + l * DH, bo + l * DH, l, N);
    }

    dim3 pg(NG, NL);
    pool_kernel<<<pg, DH>>>();
    score_kernel<<<NG, 64>>>(Wp, bp, out);
}

// round 8
// speedup vs baseline: 1.3728x; 1.3474x over previous
#include <cuda_runtime.h>
#include <cuda_fp16.h>
#include <cstdint>

// ---------------- problem constants (fixed by dataset) ----------------
#define NNODES 100000
#define NEDGES 1600000
#define DH 128           // feature dim (D == H)
#define NG 512           // num graphs
#define NL 5             // total reps (input + 4 layers)
#define NLG 4            // GIN layers
#define OO 64            // output dim
#define BN_EPS 1e-5f

// ---------------- static device scratch (no allocations allowed) ------
__device__ __half g_h16[NL][(size_t)NNODES * DH];  // slot0=x16, slot l+1=h_l
__device__ __half g_pooled16[(size_t)NNODES * DH];
__device__ float g_z[(size_t)NNODES * DH];
__device__ float g_y1[(size_t)NNODES * DH];
__device__ int   g_deg[NNODES];
__device__ int   g_off[NNODES + 1];
__device__ int   g_cursor[NNODES];
__device__ int   g_srcs[NEDGES];
__device__ int   g_gstart[NG + 1];
__device__ int   g_bsum[128];
__device__ int   g_boff[129];
__device__ int   g_total;
__device__ float g_stats[NLG][2][2 * DH];   // [layer][stage][sum|sumsq]
__device__ float g_ph[NL][NG * DH];         // per-graph pooled reps
__device__ __half g_w16[8][DH * DH];        // fp16 weights [n][k]; 0-3 W1, 4-7 W2

// ---------------- helpers ----------------------------------------------
__device__ __forceinline__ uint32_t smem_u32(const void* p) {
    uint32_t a;
    asm("{ .reg .u64 t; cvta.to.shared.u64 t, %1; cvt.u32.u64 %0, t; }"
        : "=r"(a) : "l"(p));
    return a;
}

__device__ __forceinline__ void ldx4(uint32_t* r, uint32_t addr) {
    asm volatile("ldmatrix.sync.aligned.m8n8.x4.shared.b16 {%0,%1,%2,%3}, [%4];"
                 : "=r"(r[0]), "=r"(r[1]), "=r"(r[2]), "=r"(r[3]) : "r"(addr));
}

__device__ __forceinline__ void mma16816(float* c, uint32_t a0, uint32_t a1,
                                         uint32_t a2, uint32_t a3,
                                         uint32_t b0, uint32_t b1) {
    asm volatile(
        "mma.sync.aligned.m16n8k16.row.col.f32.f16.f16.f32 "
        "{%0,%1,%2,%3}, {%4,%5,%6,%7}, {%8,%9}, {%0,%1,%2,%3};"
        : "+f"(c[0]), "+f"(c[1]), "+f"(c[2]), "+f"(c[3])
        : "r"(a0), "r"(a1), "r"(a2), "r"(a3), "r"(b0), "r"(b1));
}

// smem tile geometry: 128 rows x 136 halves (272B rows, conflict-free ldmatrix)
#define LDT 136
#define SM_A 0
#define SM_B 34816                       // 128*136*2
#define SM_ST 69632
#define SMEM_BYTES (69632 + 4 * 128 * 4)

// ---------------- small utility kernels --------------------------------
__global__ void zero_kernel(int n_nodes) {
    int i = blockIdx.x * blockDim.x + threadIdx.x;
    if (i < n_nodes) g_deg[i] = 0;
    if (i < NLG * 2 * 2 * DH) ((float*)g_stats)[i] = 0.0f;
}

__global__ void hist_kernel(const int* __restrict__ dst, int E) {
    int i = blockIdx.x * blockDim.x + threadIdx.x;
    if (i < E) atomicAdd(&g_deg[dst[i]], 1);
}

__global__ void scan1_kernel(int n) {
    __shared__ int warpsum[32];
    int tid = threadIdx.x, lane = tid & 31, wid = tid >> 5;
    int i = blockIdx.x * 1024 + tid;
    int v = (i < n) ? g_deg[i] : 0;
    int xv = v;
    #pragma unroll
    for (int o = 1; o < 32; o <<= 1) {
        int t = __shfl_up_sync(0xffffffffu, xv, o);
        if (lane >= o) xv += t;
    }
    if (lane == 31) warpsum[wid] = xv;
    __syncthreads();
    if (wid == 0) {
        int w = warpsum[lane];
        int yv = w;
        #pragma unroll
        for (int o = 1; o < 32; o <<= 1) {
            int t = __shfl_up_sync(0xffffffffu, yv, o);
            if (lane >= o) yv += t;
        }
        warpsum[lane] = yv - w;
    }
    __syncthreads();
    int excl = warpsum[wid] + xv - v;
    if (i < n) g_off[i] = excl;
    if (tid == 1023) g_bsum[blockIdx.x] = excl + v;
}

__global__ void scan2_kernel(int nb) {
    __shared__ int s[128];
    int tid = threadIdx.x;
    int v = (tid < nb) ? g_bsum[tid] : 0;
    s[tid] = v;
    __syncthreads();
    #pragma unroll
    for (int o = 1; o < 128; o <<= 1) {
        int t = (tid >= o) ? s[tid - o] : 0;
        __syncthreads();
        s[tid] += t;
        __syncthreads();
    }
    g_boff[tid] = s[tid] - v;
    if (tid == nb - 1) g_total = s[tid];
}

__global__ void scan3_kernel(int n) {
    int i = blockIdx.x * blockDim.x + threadIdx.x;
    if (i < n) {
        int o = g_off[i] + g_boff[i >> 10];
        g_off[i] = o;
        g_cursor[i] = o;
    }
    if (i == 0) g_off[n] = g_total;
}

__global__ void scatter_kernel(const int* __restrict__ src,
                               const int* __restrict__ dst, int E) {
    int i = blockIdx.x * blockDim.x + threadIdx.x;
    if (i < E) {
        int p = atomicAdd(&g_cursor[dst[i]], 1);
        g_srcs[p] = src[i];
    }
}

__global__ void gbounds_kernel(const int* __restrict__ gid, int n) {
    int i = blockIdx.x * blockDim.x + threadIdx.x;
    if (i > n) return;
    if (i == 0) {
        int b = gid[0];
        for (int g = 0; g <= b; ++g) g_gstart[g] = 0;
    } else if (i == n) {
        int a = gid[n - 1];
        for (int g = a + 1; g <= NG; ++g) g_gstart[g] = n;
    } else {
        int a = gid[i - 1], b = gid[i];
        for (int g = a + 1; g <= b; ++g) g_gstart[g] = i;
    }
}

// x -> fp16 copy (slot 0)
__global__ void xconv_kernel(const float* __restrict__ x, int M) {
    int idx = blockIdx.x * blockDim.x + threadIdx.x;  // float4 index
    if (idx >= M * 32) return;
    float4 v = ((const float4*)x)[idx];
    __half2 a = __floats2half2_rn(v.x, v.y);
    __half2 b = __floats2half2_rn(v.z, v.w);
    uint2 u;
    u.x = *(uint32_t*)&a; u.y = *(uint32_t*)&b;
    ((uint2*)&g_h16[0][0])[idx] = u;
}

// weights fp32 [k][n] -> fp16 [n][k]
__global__ void wconv_kernel(const float* __restrict__ W1,
                             const float* __restrict__ W2) {
    int i = blockIdx.x * blockDim.x + threadIdx.x;
    if (i >= 8 * DH * DH) return;
    int mat = i >> 14, r = i & 16383;
    int n = r >> 7, k = r & 127;
    const float* src = (mat < 4) ? (W1 + ((size_t)mat << 14))
                                 : (W2 + ((size_t)(mat - 4) << 14));
    g_w16[mat][r] = __float2half(src[k * DH + n]);
}

// h16[l+1] = fp16(relu(bn_outer(z))) using stage-1 stats
__global__ void hconv_kernel(const float* __restrict__ z,
                             const float* __restrict__ go,
                             const float* __restrict__ bo, int l, int M) {
    __shared__ float s_scale[128], s_shift[128];
    int tid = threadIdx.x;
    if (tid < 128) {
        float inv = 1.0f / (float)M;
        float m = g_stats[l][1][tid] * inv;
        float v = g_stats[l][1][128 + tid] * inv - m * m;
        float s = __ldg(&go[tid]) * rsqrtf(v + BN_EPS);
        s_scale[tid] = s;
        s_shift[tid] = __ldg(&bo[tid]) - m * s;
    }
    __syncthreads();
    int idx = blockIdx.x * blockDim.x + tid;  // float4 index
    if (idx >= M * 32) return;
    int c = (idx & 31) * 4;
    float4 v = ((const float4*)z)[idx];
    float o0 = fmaxf(fmaf(v.x, s_scale[c + 0], s_shift[c + 0]), 0.0f);
    float o1 = fmaxf(fmaf(v.y, s_scale[c + 1], s_shift[c + 1]), 0.0f);
    float o2 = fmaxf(fmaf(v.z, s_scale[c + 2], s_shift[c + 2]), 0.0f);
    float o3 = fmaxf(fmaf(v.w, s_scale[c + 3], s_shift[c + 3]), 0.0f);
    __half2 a = __floats2half2_rn(o0, o1);
    __half2 b = __floats2half2_rn(o2, o3);
    uint2 u;
    u.x = *(uint32_t*)&a; u.y = *(uint32_t*)&b;
    ((uint2*)&g_h16[l + 1][0])[idx] = u;
}

// ---------------- aggregation: warp per node, fp16 CSR gather ----------
__global__ void agg_kernel(const __half* __restrict__ H16,
                           const float* __restrict__ eps, int l, int n) {
    int w = (blockIdx.x * blockDim.x + threadIdx.x) >> 5;
    if (w >= n) return;
    int lane = threadIdx.x & 31;
    float onepe = 1.0f + __ldg(&eps[l]);
    const uint2* hv = (const uint2*)H16;   // 32 uint2 (8B) per 256B row

    uint2 su = __ldg(&hv[(size_t)w * 32 + lane]);
    float2 f0 = __half22float2(*(__half2*)&su.x);
    float2 f1 = __half22float2(*(__half2*)&su.y);
    float4 acc = make_float4(onepe * f0.x, onepe * f0.y,
                             onepe * f1.x, onepe * f1.y);

    int s = g_off[w], e = g_off[w + 1];
    int j = s;
    for (; j + 4 <= e; j += 4) {
        int s0 = g_srcs[j], s1 = g_srcs[j + 1], s2 = g_srcs[j + 2], s3 = g_srcs[j + 3];
        uint2 u0 = __ldg(&hv[(size_t)s0 * 32 + lane]);
        uint2 u1 = __ldg(&hv[(size_t)s1 * 32 + lane]);
        uint2 u2 = __ldg(&hv[(size_t)s2 * 32 + lane]);
        uint2 u3 = __ldg(&hv[(size_t)s3 * 32 + lane]);
        float2 a0 = __half22float2(*(__half2*)&u0.x), b0 = __half22float2(*(__half2*)&u0.y);
        float2 a1 = __half22float2(*(__half2*)&u1.x), b1 = __half22float2(*(__half2*)&u1.y);
        float2 a2 = __half22float2(*(__half2*)&u2.x), b2 = __half22float2(*(__half2*)&u2.y);
        float2 a3 = __half22float2(*(__half2*)&u3.x), b3 = __half22float2(*(__half2*)&u3.y);
        acc.x += (a0.x + a1.x) + (a2.x + a3.x);
        acc.y += (a0.y + a1.y) + (a2.y + a3.y);
        acc.z += (b0.x + b1.x) + (b2.x + b3.x);
        acc.w += (b0.y + b1.y) + (b2.y + b3.y);
    }
    for (; j < e; ++j) {
        uint2 u0 = __ldg(&hv[(size_t)g_srcs[j] * 32 + lane]);
        float2 a0 = __half22float2(*(__half2*)&u0.x);
        float2 b0 = __half22float2(*(__half2*)&u0.y);
        acc.x += a0.x; acc.y += a0.y; acc.z += b0.x; acc.w += b0.y;
    }
    __half2 p0 = __floats2half2_rn(acc.x, acc.y);
    __half2 p1 = __floats2half2_rn(acc.z, acc.w);
    uint2 u;
    u.x = *(uint32_t*)&p0; u.y = *(uint32_t*)&p1;
    ((uint2*)g_pooled16)[(size_t)w * 32 + lane] = u;
}

// ---------------- single-term fp16 mma GEMM ----------------------------
// C[M,128] = f(A)[M,128] @ W16^T + bias ; f=identity on fp16 A (PRE_BN=0)
// or relu(bn(stage0)) on fp32 A (PRE_BN=1). Column stats into stage.
template <bool PRE_BN>
__global__ void __launch_bounds__(256, 2)
gemm_f16(const __half* __restrict__ A16, const float* __restrict__ A32,
         const __half* __restrict__ B16,
         const float* __restrict__ bias,
         const float* __restrict__ gamma, const float* __restrict__ beta,
         float* __restrict__ C, int l, int M) {
    extern __shared__ char sb[];
    __half* sA = (__half*)(sb + SM_A);
    __half* sB = (__half*)(sb + SM_B);
    float* s_scale = (float*)(sb + SM_ST);
    float* s_shift = s_scale + 128;
    float* s_sum   = s_shift + 128;
    float* s_sq    = s_sum + 128;

    int tid = threadIdx.x;
    if (tid < 128) { s_sum[tid] = 0.0f; s_sq[tid] = 0.0f; }
    if (PRE_BN && tid < 128) {
        float inv = 1.0f / (float)M;
        float m = g_stats[l][0][tid] * inv;
        float v = g_stats[l][0][128 + tid] * inv - m * m;
        float s = __ldg(&gamma[tid]) * rsqrtf(v + BN_EPS);
        s_scale[tid] = s;
        s_shift[tid] = __ldg(&beta[tid]) - m * s;
    }

    // ---- stage B ([n][k] fp16, 8192 u32) ----
    const uint32_t* bsrc = (const uint32_t*)B16;
    #pragma unroll
    for (int it = 0; it < 32; ++it) {
        int i = tid + it * 256;
        int n = i >> 6, kp = i & 63;
        *(uint32_t*)&sB[n * LDT + kp * 2] = bsrc[i];
    }
    __syncthreads();   // scale/shift ready (PRE_BN)

    // ---- stage A (128 rows) ----
    int row0 = blockIdx.x * 128;
    if (PRE_BN) {
        const float4* A4 = (const float4*)(A32 + (size_t)row0 * DH);
        #pragma unroll
        for (int it = 0; it < 16; ++it) {
            int idx = tid + it * 256;        // 4096 float4
            int r = idx >> 5, c4 = (idx & 31) * 4;
            float4 v = make_float4(0.f, 0.f, 0.f, 0.f);
            if (row0 + r < M) v = A4[idx];
            v.x = fmaxf(fmaf(v.x, s_scale[c4 + 0], s_shift[c4 + 0]), 0.0f);
            v.y = fmaxf(fmaf(v.y, s_scale[c4 + 1], s_shift[c4 + 1]), 0.0f);
            v.z = fmaxf(fmaf(v.z, s_scale[c4 + 2], s_shift[c4 + 2]), 0.0f);
            v.w = fmaxf(fmaf(v.w, s_scale[c4 + 3], s_shift[c4 + 3]), 0.0f);
            __half2 a = __floats2half2_rn(v.x, v.y);
            __half2 b = __floats2half2_rn(v.z, v.w);
            uint2 u;
            u.x = *(uint32_t*)&a; u.y = *(uint32_t*)&b;
            *(uint2*)&sA[r * LDT + c4] = u;
        }
    } else {
        const uint2* A8 = (const uint2*)(A16 + (size_t)row0 * DH);
        #pragma unroll
        for (int it = 0; it < 16; ++it) {
            int idx = tid + it * 256;        // 4096 uint2
            int r = idx >> 5, c4 = (idx & 31) * 4;
            uint2 u = make_uint2(0u, 0u);
            if (row0 + r < M) u = A8[idx];
            *(uint2*)&sA[r * LDT + c4] = u;
        }
    }
    __syncthreads();

    // ---- warp tiling: 8 warps = 4(m) x 2(n), each 32(m) x 64(n) ----
    int w = tid >> 5, lane = tid & 31;
    int mw = (w >> 1) * 32, nw = (w & 1) * 64;
    uint32_t base = smem_u32(sb);
    uint32_t ab = base + SM_A * 0 +
                  ((mw + (lane & 15)) * LDT + ((lane >> 4) * 8)) * 2;
    uint32_t bb = base + SM_B +
                  ((nw + (lane & 7) + ((lane >> 4) << 3)) * LDT
                   + (((lane >> 3) & 1) * 8)) * 2;

    float acc[2][8][4];
    #pragma unroll
    for (int i = 0; i < 2; ++i)
        #pragma unroll
        for (int j = 0; j < 8; ++j)
            #pragma unroll
            for (int k = 0; k < 4; ++k) acc[i][j][k] = 0.0f;

    #pragma unroll
    for (int ks = 0; ks < 8; ++ks) {
        uint32_t a0[4], a1[4], b0[4], b1[4], b2[4], b3[4];
        ldx4(a0, ab + ks * 32);
        ldx4(a1, ab + 16 * LDT * 2 + ks * 32);
        ldx4(b0, bb + ks * 32);
        ldx4(b1, bb + 16 * LDT * 2 + ks * 32);
        ldx4(b2, bb + 32 * LDT * 2 + ks * 32);
        ldx4(b3, bb + 48 * LDT * 2 + ks * 32);
        #pragma unroll
        for (int mf = 0; mf < 2; ++mf) {
            uint32_t* a = mf ? a1 : a0;
            mma16816(acc[mf][0], a[0], a[1], a[2], a[3], b0[0], b0[1]);
            mma16816(acc[mf][1], a[0], a[1], a[2], a[3], b0[2], b0[3]);
            mma16816(acc[mf][2], a[0], a[1], a[2], a[3], b1[0], b1[1]);
            mma16816(acc[mf][3], a[0], a[1], a[2], a[3], b1[2], b1[3]);
            mma16816(acc[mf][4], a[0], a[1], a[2], a[3], b2[0], b2[1]);
            mma16816(acc[mf][5], a[0], a[1], a[2], a[3], b2[2], b2[3]);
            mma16816(acc[mf][6], a[0], a[1], a[2], a[3], b3[0], b3[1]);
            mma16816(acc[mf][7], a[0], a[1], a[2], a[3], b3[2], b3[3]);
        }
    }

    // ---- epilogue: bias, direct store, column stats ----
    #pragma unroll
    for (int nf = 0; nf < 8; ++nf) {
        int col = nw + nf * 8 + (lane & 3) * 2;
        float bx = __ldg(&bias[col]), by = __ldg(&bias[col + 1]);
        float cs0 = 0.f, cs1 = 0.f, cq0 = 0.f, cq1 = 0.f;
        #pragma unroll
        for (int mf = 0; mf < 2; ++mf) {
            int r0 = row0 + mw + mf * 16 + (lane >> 2);
            float v0 = acc[mf][nf][0] + bx, v1 = acc[mf][nf][1] + by;
            float v2 = acc[mf][nf][2] + bx, v3 = acc[mf][nf][3] + by;
            if (r0 < M) {
                *(float2*)&C[(size_t)r0 * DH + col] = make_float2(v0, v1);
                cs0 += v0; cs1 += v1; cq0 += v0 * v0; cq1 += v1 * v1;
            }
            if (r0 + 8 < M) {
                *(float2*)&C[(size_t)(r0 + 8) * DH + col] = make_float2(v2, v3);
                cs0 += v2; cs1 += v3; cq0 += v2 * v2; cq1 += v3 * v3;
            }
        }
        atomicAdd(&s_sum[col], cs0);
        atomicAdd(&s_sum[col + 1], cs1);
        atomicAdd(&s_sq[col], cq0);
        atomicAdd(&s_sq[col + 1], cq1);
    }
    __syncthreads();
    const int stage = PRE_BN ? 1 : 0;
    if (tid < 128) {
        atomicAdd(&g_stats[l][stage][tid], s_sum[tid]);
        atomicAdd(&g_stats[l][stage][128 + tid], s_sq[tid]);
    }
}

// ---------------- per-graph pooling over fp16 reps ---------------------
__global__ void pool_kernel() {
    int g = blockIdx.x, lp = blockIdx.y, c = threadIdx.x;   // 128 threads
    int s = g_gstart[g], e = g_gstart[g + 1];
    const __half* h = &g_h16[lp][0];
    float acc = 0.0f;
    int r = s;
    for (; r + 4 <= e; r += 4) {
        acc += __half2float(__ldg(&h[(size_t)(r + 0) * DH + c]));
        acc += __half2float(__ldg(&h[(size_t)(r + 1) * DH + c]));
        acc += __half2float(__ldg(&h[(size_t)(r + 2) * DH + c]));
        acc += __half2float(__ldg(&h[(size_t)(r + 3) * DH + c]));
    }
    for (; r < e; ++r)
        acc += __half2float(__ldg(&h[(size_t)r * DH + c]));
    g_ph[lp][g * DH + c] = acc;
}

// ---------------- final score: 512 x 64 --------------------------------
__global__ void score_kernel(const float* __restrict__ Wp,
                             const float* __restrict__ bp,
                             float* __restrict__ out) {
    int g = blockIdx.x;
    __shared__ float sph[NL * DH];
    for (int i = threadIdx.x; i < NL * DH; i += blockDim.x) {
        int l = i / DH, c = i % DH;
        sph[i] = g_ph[l][g * DH + c];
    }
    __syncthreads();
    int o = threadIdx.x;  // 64 threads
    float acc = 0.0f;
    for (int l = 0; l < NL; ++l) {
        acc += __ldg(&bp[l * OO + o]);
        const float* Wl = Wp + (size_t)l * DH * OO;
        #pragma unroll 4
        for (int c = 0; c < DH; ++c)
            acc = fmaf(sph[l * DH + c], __ldg(&Wl[c * OO + o]), acc);
    }
    out[g * OO + o] = acc;
}

// ---------------- launcher ---------------------------------------------
extern "C" void kernel_launch(void* const* d_in, const int* in_sizes, int n_in,
                              void* d_out, int out_size) {
    const float* x   = (const float*)d_in[0];
    const int*   src = (const int*)d_in[1];
    const int*   dst = (const int*)d_in[2];
    const int*   gid = (const int*)d_in[3];
    const float* eps = (const float*)d_in[5];
    const float* W1  = (const float*)d_in[6];
    const float* b1  = (const float*)d_in[7];
    const float* gm  = (const float*)d_in[8];
    const float* bm  = (const float*)d_in[9];
    const float* W2  = (const float*)d_in[10];
    const float* b2  = (const float*)d_in[11];
    const float* go  = (const float*)d_in[12];
    const float* bo  = (const float*)d_in[13];
    const float* Wp  = (const float*)d_in[14];
    const float* bp  = (const float*)d_in[15];
    float* out = (float*)d_out;

    int N = in_sizes[0] / DH;   // 100000
    int E = in_sizes[1];        // 1600000

    float *y1, *z;
    __half *h16, *pooled16, *w16;
    cudaGetSymbolAddress((void**)&y1, g_y1);
    cudaGetSymbolAddress((void**)&z, g_z);
    cudaGetSymbolAddress((void**)&h16, g_h16);
    cudaGetSymbolAddress((void**)&pooled16, g_pooled16);
    cudaGetSymbolAddress((void**)&w16, g_w16);

    static bool attr_done = false;
    if (!attr_done) {
        cudaFuncSetAttribute(gemm_f16<false>,
                             cudaFuncAttributeMaxDynamicSharedMemorySize, SMEM_BYTES);
        cudaFuncSetAttribute(gemm_f16<true>,
                             cudaFuncAttributeMaxDynamicSharedMemorySize, SMEM_BYTES);
        attr_done = true;
    }

    int nb = (N + 1023) / 1024;
    int elemGrid = (N * 32 + 255) / 256;

    zero_kernel<<<(N + 255) / 256, 256>>>(N);
    hist_kernel<<<(E + 255) / 256, 256>>>(dst, E);
    scan1_kernel<<<nb, 1024>>>(N);
    scan2_kernel<<<1, 128>>>(nb);
    scan3_kernel<<<(N + 255) / 256, 256>>>(N);
    scatter_kernel<<<(E + 255) / 256, 256>>>(src, dst, E);
    gbounds_kernel<<<(N + 1 + 255) / 256, 256>>>(gid, N);
    xconv_kernel<<<elemGrid, 256>>>(x, N);
    wconv_kernel<<<(8 * DH * DH + 255) / 256, 256>>>(W1, W2);

    int gemmGrid = (N + 127) / 128;
    int aggGrid  = (N * 32 + 255) / 256;  // warp per node

    for (int l = 0; l < NLG; ++l) {
        const __half* hin = h16 + (size_t)l * (size_t)NNODES * DH;
        agg_kernel<<<aggGrid, 256>>>(hin, eps, l, N);
        gemm_f16<false><<<gemmGrid, 256, SMEM_BYTES>>>(
            pooled16, nullptr, w16 + (size_t)l * DH * DH,
            b1 + l * DH, nullptr, nullptr, y1, l, N);
        gemm_f16<true><<<gemmGrid, 256, SMEM_BYTES>>>(
            nullptr, y1, w16 + (size_t)(4 + l) * DH * DH,
            b2 + l * DH, gm + l * DH, bm + l * DH, z, l, N);
        hconv_kernel<<<elemGrid, 256>>>(z, go + l * DH, bo + l * DH, l, N);
    }

    dim3 pg(NG, NL);
    pool_kernel<<<pg, DH>>>();
    score_kernel<<<NG, 64>>>(Wp, bp, out);
}

// round 9
// speedup vs baseline: 1.3887x; 1.0116x over previous
#include <cuda_runtime.h>
#include <cuda_fp16.h>
#include <cstdint>

// ---------------- problem constants (fixed by dataset) ----------------
#define NNODES 100000
#define NEDGES 1600000
#define DH 128           // feature dim (D == H)
#define NG 512           // num graphs
#define NL 5             // total reps (input + 4 layers)
#define NLG 4            // GIN layers
#define OO 64            // output dim
#define BN_EPS 1e-5f

// ---------------- static device scratch (no allocations allowed) ------
__device__ __half g_x16[(size_t)NNODES * DH];
__device__ __half g_z16[NLG][(size_t)NNODES * DH];   // fp16 z per layer
__device__ __half g_pooled16[(size_t)NNODES * DH];
__device__ __half g_y16[(size_t)NNODES * DH];
__device__ int   g_deg[NNODES];
__device__ int   g_off[NNODES + 1];
__device__ int   g_cursor[NNODES];
__device__ int   g_srcs[NEDGES];
__device__ int   g_gstart[NG + 1];
__device__ int   g_bsum[128];
__device__ int   g_boff[129];
__device__ int   g_total;
__device__ float g_stats[NLG][2][2 * DH];   // [layer][stage][sum|sumsq]
__device__ float g_ph[NL][NG * DH];         // per-graph pooled reps
__device__ __half g_w16[8][DH * DH];        // fp16 weights [n][k]; 0-3 W1, 4-7 W2

// ---------------- helpers ----------------------------------------------
__device__ __forceinline__ uint32_t smem_u32(const void* p) {
    uint32_t a;
    asm("{ .reg .u64 t; cvta.to.shared.u64 t, %1; cvt.u32.u64 %0, t; }"
        : "=r"(a) : "l"(p));
    return a;
}

__device__ __forceinline__ void ldx4(uint32_t* r, uint32_t addr) {
    asm volatile("ldmatrix.sync.aligned.m8n8.x4.shared.b16 {%0,%1,%2,%3}, [%4];"
                 : "=r"(r[0]), "=r"(r[1]), "=r"(r[2]), "=r"(r[3]) : "r"(addr));
}

__device__ __forceinline__ void mma16816(float* c, uint32_t a0, uint32_t a1,
                                         uint32_t a2, uint32_t a3,
                                         uint32_t b0, uint32_t b1) {
    asm volatile(
        "mma.sync.aligned.m16n8k16.row.col.f32.f16.f16.f32 "
        "{%0,%1,%2,%3}, {%4,%5,%6,%7}, {%8,%9}, {%0,%1,%2,%3};"
        : "+f"(c[0]), "+f"(c[1]), "+f"(c[2]), "+f"(c[3])
        : "r"(a0), "r"(a1), "r"(a2), "r"(a3), "r"(b0), "r"(b1));
}

// smem tile geometry: 128 rows x 136 halves (272B rows, conflict-free ldmatrix)
#define LDT 136
#define SM_A 0
#define SM_B 34816                       // 128*136*2
#define SM_ST 69632
#define SMEM_BYTES (69632 + 4 * 128 * 4)

// ---------------- small utility kernels --------------------------------
__global__ void zero_kernel(int n_nodes) {
    int i = blockIdx.x * blockDim.x + threadIdx.x;
    if (i < n_nodes) g_deg[i] = 0;
    if (i < NLG * 2 * 2 * DH) ((float*)g_stats)[i] = 0.0f;
}

__global__ void hist_kernel(const int* __restrict__ dst, int E) {
    int i = blockIdx.x * blockDim.x + threadIdx.x;
    if (i < E) atomicAdd(&g_deg[dst[i]], 1);
}

__global__ void scan1_kernel(int n) {
    __shared__ int warpsum[32];
    int tid = threadIdx.x, lane = tid & 31, wid = tid >> 5;
    int i = blockIdx.x * 1024 + tid;
    int v = (i < n) ? g_deg[i] : 0;
    int xv = v;
    #pragma unroll
    for (int o = 1; o < 32; o <<= 1) {
        int t = __shfl_up_sync(0xffffffffu, xv, o);
        if (lane >= o) xv += t;
    }
    if (lane == 31) warpsum[wid] = xv;
    __syncthreads();
    if (wid == 0) {
        int w = warpsum[lane];
        int yv = w;
        #pragma unroll
        for (int o = 1; o < 32; o <<= 1) {
            int t = __shfl_up_sync(0xffffffffu, yv, o);
            if (lane >= o) yv += t;
        }
        warpsum[lane] = yv - w;
    }
    __syncthreads();
    int excl = warpsum[wid] + xv - v;
    if (i < n) g_off[i] = excl;
    if (tid == 1023) g_bsum[blockIdx.x] = excl + v;
}

__global__ void scan2_kernel(int nb) {
    __shared__ int s[128];
    int tid = threadIdx.x;
    int v = (tid < nb) ? g_bsum[tid] : 0;
    s[tid] = v;
    __syncthreads();
    #pragma unroll
    for (int o = 1; o < 128; o <<= 1) {
        int t = (tid >= o) ? s[tid - o] : 0;
        __syncthreads();
        s[tid] += t;
        __syncthreads();
    }
    g_boff[tid] = s[tid] - v;
    if (tid == nb - 1) g_total = s[tid];
}

__global__ void scan3_kernel(int n) {
    int i = blockIdx.x * blockDim.x + threadIdx.x;
    if (i < n) {
        int o = g_off[i] + g_boff[i >> 10];
        g_off[i] = o;
        g_cursor[i] = o;
    }
    if (i == 0) g_off[n] = g_total;
}

__global__ void scatter_kernel(const int* __restrict__ src,
                               const int* __restrict__ dst, int E) {
    int i = blockIdx.x * blockDim.x + threadIdx.x;
    if (i < E) {
        int p = atomicAdd(&g_cursor[dst[i]], 1);
        g_srcs[p] = src[i];
    }
}

__global__ void gbounds_kernel(const int* __restrict__ gid, int n) {
    int i = blockIdx.x * blockDim.x + threadIdx.x;
    if (i > n) return;
    if (i == 0) {
        int b = gid[0];
        for (int g = 0; g <= b; ++g) g_gstart[g] = 0;
    } else if (i == n) {
        int a = gid[n - 1];
        for (int g = a + 1; g <= NG; ++g) g_gstart[g] = n;
    } else {
        int a = gid[i - 1], b = gid[i];
        for (int g = a + 1; g <= b; ++g) g_gstart[g] = i;
    }
}

// x -> fp16
__global__ void xconv_kernel(const float* __restrict__ x, int M) {
    int idx = blockIdx.x * blockDim.x + threadIdx.x;  // float4 index
    if (idx >= M * 32) return;
    float4 v = ((const float4*)x)[idx];
    __half2 a = __floats2half2_rn(v.x, v.y);
    __half2 b = __floats2half2_rn(v.z, v.w);
    uint2 u;
    u.x = *(uint32_t*)&a; u.y = *(uint32_t*)&b;
    ((uint2*)g_x16)[idx] = u;
}

// weights fp32 [k][n] -> fp16 [n][k]
__global__ void wconv_kernel(const float* __restrict__ W1,
                             const float* __restrict__ W2) {
    int i = blockIdx.x * blockDim.x + threadIdx.x;
    if (i >= 8 * DH * DH) return;
    int mat = i >> 14, r = i & 16383;
    int n = r >> 7, k = r & 127;
    const float* src = (mat < 4) ? (W1 + ((size_t)mat << 14))
                                 : (W2 + ((size_t)(mat - 4) << 14));
    g_w16[mat][r] = __float2half(src[k * DH + n]);
}

// ---------------- aggregation: warp per node, fp16 CSR gather ----------
// FIRST: reads x16 plain. Else: reads z16[l-1], applying outer-BN affine+ReLU
// (scale/shift from stage-1 stats of layer l-1) on the fly.
template <bool FIRST>
__global__ void agg_kernel(const __half* __restrict__ H16,
                           const float* __restrict__ go_prev,
                           const float* __restrict__ bo_prev,
                           const float* __restrict__ eps, int l, int n) {
    __shared__ float s_sc[128], s_sh[128];
    int tid = threadIdx.x;
    if (!FIRST) {
        if (tid < 128) {
            float inv = 1.0f / (float)n;
            float m = g_stats[l - 1][1][tid] * inv;
            float v = g_stats[l - 1][1][128 + tid] * inv - m * m;
            float s = __ldg(&go_prev[tid]) * rsqrtf(v + BN_EPS);
            s_sc[tid] = s;
            s_sh[tid] = __ldg(&bo_prev[tid]) - m * s;
        }
        __syncthreads();
    }
    int w = (blockIdx.x * blockDim.x + tid) >> 5;
    if (w >= n) return;
    int lane = tid & 31;
    float4 sc = make_float4(1.f, 1.f, 1.f, 1.f);
    float4 sh = make_float4(0.f, 0.f, 0.f, 0.f);
    if (!FIRST) {
        sc = *(float4*)&s_sc[lane * 4];
        sh = *(float4*)&s_sh[lane * 4];
    }
    float onepe = 1.0f + __ldg(&eps[l]);
    const uint2* hv = (const uint2*)H16;   // 32 uint2 (8B) per 256B row

    uint2 su = __ldg(&hv[(size_t)w * 32 + lane]);
    float2 f0 = __half22float2(*(__half2*)&su.x);
    float2 f1 = __half22float2(*(__half2*)&su.y);
    float4 vsv = make_float4(f0.x, f0.y, f1.x, f1.y);
    if (!FIRST) {
        vsv.x = fmaxf(fmaf(vsv.x, sc.x, sh.x), 0.0f);
        vsv.y = fmaxf(fmaf(vsv.y, sc.y, sh.y), 0.0f);
        vsv.z = fmaxf(fmaf(vsv.z, sc.z, sh.z), 0.0f);
        vsv.w = fmaxf(fmaf(vsv.w, sc.w, sh.w), 0.0f);
    }
    float4 acc = make_float4(onepe * vsv.x, onepe * vsv.y,
                             onepe * vsv.z, onepe * vsv.w);

    int s = g_off[w], e = g_off[w + 1];
    int j = s;
    for (; j + 8 <= e; j += 8) {
        uint2 u[8];
        #pragma unroll
        for (int q = 0; q < 8; ++q)
            u[q] = __ldg(&hv[(size_t)g_srcs[j + q] * 32 + lane]);
        #pragma unroll
        for (int q = 0; q < 8; ++q) {
            float2 a0 = __half22float2(*(__half2*)&u[q].x);
            float2 b0 = __half22float2(*(__half2*)&u[q].y);
            float vx = a0.x, vy = a0.y, vz = b0.x, vw = b0.y;
            if (!FIRST) {
                vx = fmaxf(fmaf(vx, sc.x, sh.x), 0.0f);
                vy = fmaxf(fmaf(vy, sc.y, sh.y), 0.0f);
                vz = fmaxf(fmaf(vz, sc.z, sh.z), 0.0f);
                vw = fmaxf(fmaf(vw, sc.w, sh.w), 0.0f);
            }
            acc.x += vx; acc.y += vy; acc.z += vz; acc.w += vw;
        }
    }
    for (; j < e; ++j) {
        uint2 u0 = __ldg(&hv[(size_t)g_srcs[j] * 32 + lane]);
        float2 a0 = __half22float2(*(__half2*)&u0.x);
        float2 b0 = __half22float2(*(__half2*)&u0.y);
        float vx = a0.x, vy = a0.y, vz = b0.x, vw = b0.y;
        if (!FIRST) {
            vx = fmaxf(fmaf(vx, sc.x, sh.x), 0.0f);
            vy = fmaxf(fmaf(vy, sc.y, sh.y), 0.0f);
            vz = fmaxf(fmaf(vz, sc.z, sh.z), 0.0f);
            vw = fmaxf(fmaf(vw, sc.w, sh.w), 0.0f);
        }
        acc.x += vx; acc.y += vy; acc.z += vz; acc.w += vw;
    }
    __half2 p0 = __floats2half2_rn(acc.x, acc.y);
    __half2 p1 = __floats2half2_rn(acc.z, acc.w);
    uint2 u;
    u.x = *(uint32_t*)&p0; u.y = *(uint32_t*)&p1;
    ((uint2*)g_pooled16)[(size_t)w * 32 + lane] = u;
}

// ---------------- single-term fp16 mma GEMM, fp16 in/out ---------------
// C16[M,128] = f(A16)[M,128] @ W16^T + bias ; f = identity (PRE_BN=0) or
// relu(bn(stage0)) (PRE_BN=1, affine on fp16 A). Column stats -> stage.
template <bool PRE_BN>
__global__ void __launch_bounds__(256, 2)
gemm_f16(const __half* __restrict__ A16, const __half* __restrict__ B16,
         const float* __restrict__ bias,
         const float* __restrict__ gamma, const float* __restrict__ beta,
         __half* __restrict__ C16, int l, int M) {
    extern __shared__ char sb[];
    __half* sA = (__half*)(sb + SM_A);
    __half* sB = (__half*)(sb + SM_B);
    float* s_scale = (float*)(sb + SM_ST);
    float* s_shift = s_scale + 128;
    float* s_sum   = s_shift + 128;
    float* s_sq    = s_sum + 128;

    int tid = threadIdx.x;
    if (tid < 128) { s_sum[tid] = 0.0f; s_sq[tid] = 0.0f; }
    if (PRE_BN && tid < 128) {
        float inv = 1.0f / (float)M;
        float m = g_stats[l][0][tid] * inv;
        float v = g_stats[l][0][128 + tid] * inv - m * m;
        float s = __ldg(&gamma[tid]) * rsqrtf(v + BN_EPS);
        s_scale[tid] = s;
        s_shift[tid] = __ldg(&beta[tid]) - m * s;
    }

    // ---- stage B ([n][k] fp16, 8192 u32) ----
    const uint32_t* bsrc = (const uint32_t*)B16;
    #pragma unroll
    for (int it = 0; it < 32; ++it) {
        int i = tid + it * 256;
        int n = i >> 6, kp = i & 63;
        *(uint32_t*)&sB[n * LDT + kp * 2] = bsrc[i];
    }
    __syncthreads();   // scale/shift ready (PRE_BN)

    // ---- stage A (128 rows fp16; optional affine+relu) ----
    int row0 = blockIdx.x * 128;
    const uint2* A8 = (const uint2*)(A16 + (size_t)row0 * DH);
    #pragma unroll
    for (int it = 0; it < 16; ++it) {
        int idx = tid + it * 256;            // 4096 uint2
        int r = idx >> 5, c4 = (idx & 31) * 4;
        uint2 u = make_uint2(0u, 0u);
        if (row0 + r < M) u = A8[idx];
        if (PRE_BN) {
            float2 a = __half22float2(*(__half2*)&u.x);
            float2 b = __half22float2(*(__half2*)&u.y);
            a.x = fmaxf(fmaf(a.x, s_scale[c4 + 0], s_shift[c4 + 0]), 0.0f);
            a.y = fmaxf(fmaf(a.y, s_scale[c4 + 1], s_shift[c4 + 1]), 0.0f);
            b.x = fmaxf(fmaf(b.x, s_scale[c4 + 2], s_shift[c4 + 2]), 0.0f);
            b.y = fmaxf(fmaf(b.y, s_scale[c4 + 3], s_shift[c4 + 3]), 0.0f);
            __half2 ha = __floats2half2_rn(a.x, a.y);
            __half2 hb = __floats2half2_rn(b.x, b.y);
            u.x = *(uint32_t*)&ha; u.y = *(uint32_t*)&hb;
        }
        *(uint2*)&sA[r * LDT + c4] = u;
    }
    __syncthreads();

    // ---- warp tiling: 8 warps = 4(m) x 2(n), each 32(m) x 64(n) ----
    int w = tid >> 5, lane = tid & 31;
    int mw = (w >> 1) * 32, nw = (w & 1) * 64;
    uint32_t base = smem_u32(sb);
    uint32_t ab = base + ((mw + (lane & 15)) * LDT + ((lane >> 4) * 8)) * 2;
    uint32_t bb = base + SM_B +
                  ((nw + (lane & 7) + ((lane >> 4) << 3)) * LDT
                   + (((lane >> 3) & 1) * 8)) * 2;

    float acc[2][8][4];
    #pragma unroll
    for (int i = 0; i < 2; ++i)
        #pragma unroll
        for (int j = 0; j < 8; ++j)
            #pragma unroll
            for (int k = 0; k < 4; ++k) acc[i][j][k] = 0.0f;

    #pragma unroll
    for (int ks = 0; ks < 8; ++ks) {
        uint32_t a0[4], a1[4], b0[4], b1[4], b2[4], b3[4];
        ldx4(a0, ab + ks * 32);
        ldx4(a1, ab + 16 * LDT * 2 + ks * 32);
        ldx4(b0, bb + ks * 32);
        ldx4(b1, bb + 16 * LDT * 2 + ks * 32);
        ldx4(b2, bb + 32 * LDT * 2 + ks * 32);
        ldx4(b3, bb + 48 * LDT * 2 + ks * 32);
        #pragma unroll
        for (int mf = 0; mf < 2; ++mf) {
            uint32_t* a = mf ? a1 : a0;
            mma16816(acc[mf][0], a[0], a[1], a[2], a[3], b0[0], b0[1]);
            mma16816(acc[mf][1], a[0], a[1], a[2], a[3], b0[2], b0[3]);
            mma16816(acc[mf][2], a[0], a[1], a[2], a[3], b1[0], b1[1]);
            mma16816(acc[mf][3], a[0], a[1], a[2], a[3], b1[2], b1[3]);
            mma16816(acc[mf][4], a[0], a[1], a[2], a[3], b2[0], b2[1]);
            mma16816(acc[mf][5], a[0], a[1], a[2], a[3], b2[2], b2[3]);
            mma16816(acc[mf][6], a[0], a[1], a[2], a[3], b3[0], b3[1]);
            mma16816(acc[mf][7], a[0], a[1], a[2], a[3], b3[2], b3[3]);
        }
    }

    // ---- epilogue: bias, fp16 store, column stats (fp32, pre-rounding) ----
    #pragma unroll
    for (int nf = 0; nf < 8; ++nf) {
        int col = nw + nf * 8 + (lane & 3) * 2;
        float bx = __ldg(&bias[col]), by = __ldg(&bias[col + 1]);
        float cs0 = 0.f, cs1 = 0.f, cq0 = 0.f, cq1 = 0.f;
        #pragma unroll
        for (int mf = 0; mf < 2; ++mf) {
            int r0 = row0 + mw + mf * 16 + (lane >> 2);
            float v0 = acc[mf][nf][0] + bx, v1 = acc[mf][nf][1] + by;
            float v2 = acc[mf][nf][2] + bx, v3 = acc[mf][nf][3] + by;
            if (r0 < M) {
                __half2 h = __floats2half2_rn(v0, v1);
                *(uint32_t*)&C16[(size_t)r0 * DH + col] = *(uint32_t*)&h;
                cs0 += v0; cs1 += v1; cq0 += v0 * v0; cq1 += v1 * v1;
            }
            if (r0 + 8 < M) {
                __half2 h = __floats2half2_rn(v2, v3);
                *(uint32_t*)&C16[(size_t)(r0 + 8) * DH + col] = *(uint32_t*)&h;
                cs0 += v2; cs1 += v3; cq0 += v2 * v2; cq1 += v3 * v3;
            }
        }
        atomicAdd(&s_sum[col], cs0);
        atomicAdd(&s_sum[col + 1], cs1);
        atomicAdd(&s_sq[col], cq0);
        atomicAdd(&s_sq[col + 1], cq1);
    }
    __syncthreads();
    const int stage = PRE_BN ? 1 : 0;
    if (tid < 128) {
        atomicAdd(&g_stats[l][stage][tid], s_sum[tid]);
        atomicAdd(&g_stats[l][stage][128 + tid], s_sq[tid]);
    }
}

// ---------------- per-graph pooling (affine+ReLU on the fly) -----------
__global__ void pool_kernel(const float* __restrict__ go,
                            const float* __restrict__ bo, int M) {
    int g = blockIdx.x, lp = blockIdx.y, c = threadIdx.x;   // 128 threads
    int s = g_gstart[g], e = g_gstart[g + 1];
    float acc = 0.0f;
    if (lp == 0) {
        const __half* h = g_x16;
        for (int r = s; r < e; ++r)
            acc += __half2float(__ldg(&h[(size_t)r * DH + c]));
    } else {
        int l = lp - 1;
        const __half* z = &g_z16[l][0];
        float inv = 1.0f / (float)M;
        float m = g_stats[l][1][c] * inv;
        float v = g_stats[l][1][128 + c] * inv - m * m;
        float scl = __ldg(&go[l * DH + c]) * rsqrtf(v + BN_EPS);
        float shf = __ldg(&bo[l * DH + c]) - m * scl;
        for (int r = s; r < e; ++r)
            acc += fmaxf(fmaf(__half2float(__ldg(&z[(size_t)r * DH + c])),
                              scl, shf), 0.0f);
    }
    g_ph[lp][g * DH + c] = acc;
}

// ---------------- final score: 512 x 64 --------------------------------
__global__ void score_kernel(const float* __restrict__ Wp,
                             const float* __restrict__ bp,
                             float* __restrict__ out) {
    int g = blockIdx.x;
    __shared__ float sph[NL * DH];
    for (int i = threadIdx.x; i < NL * DH; i += blockDim.x) {
        int l = i / DH, c = i % DH;
        sph[i] = g_ph[l][g * DH + c];
    }
    __syncthreads();
    int o = threadIdx.x;  // 64 threads
    float acc = 0.0f;
    for (int l = 0; l < NL; ++l) {
        acc += __ldg(&bp[l * OO + o]);
        const float* Wl = Wp + (size_t)l * DH * OO;
        #pragma unroll 4
        for (int c = 0; c < DH; ++c)
            acc = fmaf(sph[l * DH + c], __ldg(&Wl[c * OO + o]), acc);
    }
    out[g * OO + o] = acc;
}

// ---------------- launcher ---------------------------------------------
extern "C" void kernel_launch(void* const* d_in, const int* in_sizes, int n_in,
                              void* d_out, int out_size) {
    const float* x   = (const float*)d_in[0];
    const int*   src = (const int*)d_in[1];
    const int*   dst = (const int*)d_in[2];
    const int*   gid = (const int*)d_in[3];
    const float* eps = (const float*)d_in[5];
    const float* W1  = (const float*)d_in[6];
    const float* b1  = (const float*)d_in[7];
    const float* gm  = (const float*)d_in[8];
    const float* bm  = (const float*)d_in[9];
    const float* W2  = (const float*)d_in[10];
    const float* b2  = (const float*)d_in[11];
    const float* go  = (const float*)d_in[12];
    const float* bo  = (const float*)d_in[13];
    const float* Wp  = (const float*)d_in[14];
    const float* bp  = (const float*)d_in[15];
    float* out = (float*)d_out;

    int N = in_sizes[0] / DH;   // 100000
    int E = in_sizes[1];        // 1600000

    __half *x16, *z16, *pooled16, *y16, *w16;
    cudaGetSymbolAddress((void**)&x16, g_x16);
    cudaGetSymbolAddress((void**)&z16, g_z16);
    cudaGetSymbolAddress((void**)&pooled16, g_pooled16);
    cudaGetSymbolAddress((void**)&y16, g_y16);
    cudaGetSymbolAddress((void**)&w16, g_w16);

    static bool attr_done = false;
    if (!attr_done) {
        cudaFuncSetAttribute(gemm_f16<false>,
                             cudaFuncAttributeMaxDynamicSharedMemorySize, SMEM_BYTES);
        cudaFuncSetAttribute(gemm_f16<true>,
                             cudaFuncAttributeMaxDynamicSharedMemorySize, SMEM_BYTES);
        attr_done = true;
    }

    int nb = (N + 1023) / 1024;
    int elemGrid = (N * 32 + 255) / 256;

    zero_kernel<<<(N + 255) / 256, 256>>>(N);
    hist_kernel<<<(E + 255) / 256, 256>>>(dst, E);
    scan1_kernel<<<nb, 1024>>>(N);
    scan2_kernel<<<1, 128>>>(nb);
    scan3_kernel<<<(N + 255) / 256, 256>>>(N);
    scatter_kernel<<<(E + 255) / 256, 256>>>(src, dst, E);
    gbounds_kernel<<<(N + 1 + 255) / 256, 256>>>(gid, N);
    xconv_kernel<<<elemGrid, 256>>>(x, N);
    wconv_kernel<<<(8 * DH * DH + 255) / 256, 256>>>(W1, W2);

    int gemmGrid = (N + 127) / 128;
    int aggGrid  = (N * 32 + 255) / 256;  // warp per node

    for (int l = 0; l < NLG; ++l) {
        __half* zl = z16 + (size_t)l * (size_t)NNODES * DH;
        if (l == 0) {
            agg_kernel<true><<<aggGrid, 256>>>(x16, nullptr, nullptr, eps, l, N);
        } else {
            const __half* zp = z16 + (size_t)(l - 1) * (size_t)NNODES * DH;
            agg_kernel<false><<<aggGrid, 256>>>(zp, go + (l - 1) * DH,
                                                bo + (l - 1) * DH, eps, l, N);
        }
        gemm_f16<false><<<gemmGrid, 256, SMEM_BYTES>>>(
            pooled16, w16 + (size_t)l * DH * DH,
            b1 + l * DH, nullptr, nullptr, y16, l, N);
        gemm_f16<true><<<gemmGrid, 256, SMEM_BYTES>>>(
            y16, w16 + (size_t)(4 + l) * DH * DH,
            b2 + l * DH, gm + l * DH, bm + l * DH, zl, l, N);
    }

    dim3 pg(NG, NL);
    pool_kernel<<<pg, DH>>>(go, bo, N);
    score_kernel<<<NG, 64>>>(Wp, bp, out);
}

// round 10
// speedup vs baseline: 1.4271x; 1.0276x over previous
#include <cuda_runtime.h>
#include <cuda_fp16.h>
#include <cstdint>

// ---------------- problem constants (fixed by dataset) ----------------
#define NNODES 100000
#define NEDGES 1600000
#define DH 128           // feature dim (D == H)
#define NG 512           // num graphs
#define NL 5             // total reps (input + 4 layers)
#define NLG 4            // GIN layers
#define OO 64            // output dim
#define BN_EPS 1e-5f

// ---------------- static device scratch (no allocations allowed) ------
__device__ __half g_x16[(size_t)NNODES * DH];
__device__ __half g_z16[NLG][(size_t)NNODES * DH];   // fp16 z per layer
__device__ __half g_pooled16[(size_t)NNODES * DH];
__device__ __half g_y16[(size_t)NNODES * DH];
__device__ int   g_deg[NNODES];
__device__ int   g_off[NNODES + 1];
__device__ int   g_cursor[NNODES];
__device__ int   g_srcs[NEDGES];
__device__ int   g_gstart[NG + 1];
__device__ int   g_bsum[128];
__device__ int   g_boff[129];
__device__ int   g_total;
__device__ float g_stats[NLG][2][2 * DH];   // [layer][stage][sum|sumsq]
__device__ float g_ph[NL][NG * DH];         // per-graph pooled reps
__device__ __half g_w16[8][DH * DH];        // fp16 weights [n][k]; 0-3 W1, 4-7 W2

// ---------------- helpers ----------------------------------------------
__device__ __forceinline__ uint32_t smem_u32(const void* p) {
    uint32_t a;
    asm("{ .reg .u64 t; cvta.to.shared.u64 t, %1; cvt.u32.u64 %0, t; }"
        : "=r"(a) : "l"(p));
    return a;
}

__device__ __forceinline__ void ldx4(uint32_t* r, uint32_t addr) {
    asm volatile("ldmatrix.sync.aligned.m8n8.x4.shared.b16 {%0,%1,%2,%3}, [%4];"
                 : "=r"(r[0]), "=r"(r[1]), "=r"(r[2]), "=r"(r[3]) : "r"(addr));
}

__device__ __forceinline__ void mma16816(float* c, uint32_t a0, uint32_t a1,
                                         uint32_t a2, uint32_t a3,
                                         uint32_t b0, uint32_t b1) {
    asm volatile(
        "mma.sync.aligned.m16n8k16.row.col.f32.f16.f16.f32 "
        "{%0,%1,%2,%3}, {%4,%5,%6,%7}, {%8,%9}, {%0,%1,%2,%3};"
        : "+f"(c[0]), "+f"(c[1]), "+f"(c[2]), "+f"(c[3])
        : "r"(a0), "r"(a1), "r"(a2), "r"(a3), "r"(b0), "r"(b1));
}

// smem tile geometry: 128 rows x 136 halves (272B rows, conflict-free ldmatrix)
#define LDT 136
#define SM_A 0
#define SM_B 34816                       // 128*136*2
#define SM_ST 69632
#define SMEM_BYTES (69632 + 4 * 128 * 4)

// ---------------- small utility kernels --------------------------------
__global__ void zero_kernel(int n_nodes) {
    int i = blockIdx.x * blockDim.x + threadIdx.x;
    if (i < n_nodes) g_deg[i] = 0;
    if (i < NLG * 2 * 2 * DH) ((float*)g_stats)[i] = 0.0f;
}

__global__ void hist_kernel(const int* __restrict__ dst, int E) {
    int i = blockIdx.x * blockDim.x + threadIdx.x;
    if (i < E) atomicAdd(&g_deg[dst[i]], 1);
}

__global__ void scan1_kernel(int n) {
    __shared__ int warpsum[32];
    int tid = threadIdx.x, lane = tid & 31, wid = tid >> 5;
    int i = blockIdx.x * 1024 + tid;
    int v = (i < n) ? g_deg[i] : 0;
    int xv = v;
    #pragma unroll
    for (int o = 1; o < 32; o <<= 1) {
        int t = __shfl_up_sync(0xffffffffu, xv, o);
        if (lane >= o) xv += t;
    }
    if (lane == 31) warpsum[wid] = xv;
    __syncthreads();
    if (wid == 0) {
        int w = warpsum[lane];
        int yv = w;
        #pragma unroll
        for (int o = 1; o < 32; o <<= 1) {
            int t = __shfl_up_sync(0xffffffffu, yv, o);
            if (lane >= o) yv += t;
        }
        warpsum[lane] = yv - w;
    }
    __syncthreads();
    int excl = warpsum[wid] + xv - v;
    if (i < n) g_off[i] = excl;
    if (tid == 1023) g_bsum[blockIdx.x] = excl + v;
}

__global__ void scan2_kernel(int nb) {
    __shared__ int s[128];
    int tid = threadIdx.x;
    int v = (tid < nb) ? g_bsum[tid] : 0;
    s[tid] = v;
    __syncthreads();
    #pragma unroll
    for (int o = 1; o < 128; o <<= 1) {
        int t = (tid >= o) ? s[tid - o] : 0;
        __syncthreads();
        s[tid] += t;
        __syncthreads();
    }
    g_boff[tid] = s[tid] - v;
    if (tid == nb - 1) g_total = s[tid];
}

__global__ void scan3_kernel(int n) {
    int i = blockIdx.x * blockDim.x + threadIdx.x;
    if (i < n) {
        int o = g_off[i] + g_boff[i >> 10];
        g_off[i] = o;
        g_cursor[i] = o;
    }
    if (i == 0) g_off[n] = g_total;
}

__global__ void scatter_kernel(const int* __restrict__ src,
                               const int* __restrict__ dst, int E) {
    int i = blockIdx.x * blockDim.x + threadIdx.x;
    if (i < E) {
        int p = atomicAdd(&g_cursor[dst[i]], 1);
        g_srcs[p] = src[i];
    }
}

__global__ void gbounds_kernel(const int* __restrict__ gid, int n) {
    int i = blockIdx.x * blockDim.x + threadIdx.x;
    if (i > n) return;
    if (i == 0) {
        int b = gid[0];
        for (int g = 0; g <= b; ++g) g_gstart[g] = 0;
    } else if (i == n) {
        int a = gid[n - 1];
        for (int g = a + 1; g <= NG; ++g) g_gstart[g] = n;
    } else {
        int a = gid[i - 1], b = gid[i];
        for (int g = a + 1; g <= b; ++g) g_gstart[g] = i;
    }
}

// x -> fp16
__global__ void xconv_kernel(const float* __restrict__ x, int M) {
    int idx = blockIdx.x * blockDim.x + threadIdx.x;  // float4 index
    if (idx >= M * 32) return;
    float4 v = ((const float4*)x)[idx];
    __half2 a = __floats2half2_rn(v.x, v.y);
    __half2 b = __floats2half2_rn(v.z, v.w);
    uint2 u;
    u.x = *(uint32_t*)&a; u.y = *(uint32_t*)&b;
    ((uint2*)g_x16)[idx] = u;
}

// weights fp32 [k][n] -> fp16 [n][k]
__global__ void wconv_kernel(const float* __restrict__ W1,
                             const float* __restrict__ W2) {
    int i = blockIdx.x * blockDim.x + threadIdx.x;
    if (i >= 8 * DH * DH) return;
    int mat = i >> 14, r = i & 16383;
    int n = r >> 7, k = r & 127;
    const float* src = (mat < 4) ? (W1 + ((size_t)mat << 14))
                                 : (W2 + ((size_t)(mat - 4) << 14));
    g_w16[mat][r] = __float2half(src[k * DH + n]);
}

// ---------------- aggregation: warp per node, fp16 CSR gather ----------
template <bool FIRST>
__global__ void agg_kernel(const __half* __restrict__ H16,
                           const float* __restrict__ go_prev,
                           const float* __restrict__ bo_prev,
                           const float* __restrict__ eps, int l, int n) {
    __shared__ float s_sc[128], s_sh[128];
    int tid = threadIdx.x;
    if (!FIRST) {
        if (tid < 128) {
            float inv = 1.0f / (float)n;
            float m = g_stats[l - 1][1][tid] * inv;
            float v = g_stats[l - 1][1][128 + tid] * inv - m * m;
            float s = __ldg(&go_prev[tid]) * rsqrtf(v + BN_EPS);
            s_sc[tid] = s;
            s_sh[tid] = __ldg(&bo_prev[tid]) - m * s;
        }
        __syncthreads();
    }
    int w = (blockIdx.x * blockDim.x + tid) >> 5;
    if (w >= n) return;
    int lane = tid & 31;
    float4 sc = make_float4(1.f, 1.f, 1.f, 1.f);
    float4 sh = make_float4(0.f, 0.f, 0.f, 0.f);
    if (!FIRST) {
        sc = *(float4*)&s_sc[lane * 4];
        sh = *(float4*)&s_sh[lane * 4];
    }
    float onepe = 1.0f + __ldg(&eps[l]);
    const uint2* hv = (const uint2*)H16;   // 32 uint2 (8B) per 256B row

    uint2 su = __ldg(&hv[(size_t)w * 32 + lane]);
    float2 f0 = __half22float2(*(__half2*)&su.x);
    float2 f1 = __half22float2(*(__half2*)&su.y);
    float4 vsv = make_float4(f0.x, f0.y, f1.x, f1.y);
    if (!FIRST) {
        vsv.x = fmaxf(fmaf(vsv.x, sc.x, sh.x), 0.0f);
        vsv.y = fmaxf(fmaf(vsv.y, sc.y, sh.y), 0.0f);
        vsv.z = fmaxf(fmaf(vsv.z, sc.z, sh.z), 0.0f);
        vsv.w = fmaxf(fmaf(vsv.w, sc.w, sh.w), 0.0f);
    }
    float4 acc = make_float4(onepe * vsv.x, onepe * vsv.y,
                             onepe * vsv.z, onepe * vsv.w);

    int s = g_off[w], e = g_off[w + 1];
    int j = s;
    for (; j + 8 <= e; j += 8) {
        uint2 u[8];
        #pragma unroll
        for (int q = 0; q < 8; ++q)
            u[q] = __ldg(&hv[(size_t)g_srcs[j + q] * 32 + lane]);
        #pragma unroll
        for (int q = 0; q < 8; ++q) {
            float2 a0 = __half22float2(*(__half2*)&u[q].x);
            float2 b0 = __half22float2(*(__half2*)&u[q].y);
            float vx = a0.x, vy = a0.y, vz = b0.x, vw = b0.y;
            if (!FIRST) {
                vx = fmaxf(fmaf(vx, sc.x, sh.x), 0.0f);
                vy = fmaxf(fmaf(vy, sc.y, sh.y), 0.0f);
                vz = fmaxf(fmaf(vz, sc.z, sh.z), 0.0f);
                vw = fmaxf(fmaf(vw, sc.w, sh.w), 0.0f);
            }
            acc.x += vx; acc.y += vy; acc.z += vz; acc.w += vw;
        }
    }
    for (; j < e; ++j) {
        uint2 u0 = __ldg(&hv[(size_t)g_srcs[j] * 32 + lane]);
        float2 a0 = __half22float2(*(__half2*)&u0.x);
        float2 b0 = __half22float2(*(__half2*)&u0.y);
        float vx = a0.x, vy = a0.y, vz = b0.x, vw = b0.y;
        if (!FIRST) {
            vx = fmaxf(fmaf(vx, sc.x, sh.x), 0.0f);
            vy = fmaxf(fmaf(vy, sc.y, sh.y), 0.0f);
            vz = fmaxf(fmaf(vz, sc.z, sh.z), 0.0f);
            vw = fmaxf(fmaf(vw, sc.w, sh.w), 0.0f);
        }
        acc.x += vx; acc.y += vy; acc.z += vz; acc.w += vw;
    }
    __half2 p0 = __floats2half2_rn(acc.x, acc.y);
    __half2 p1 = __floats2half2_rn(acc.z, acc.w);
    uint2 u;
    u.x = *(uint32_t*)&p0; u.y = *(uint32_t*)&p1;
    ((uint2*)g_pooled16)[(size_t)w * 32 + lane] = u;
}

// ---------------- single-term fp16 mma GEMM, fp16 in/out ---------------
template <bool PRE_BN>
__global__ void __launch_bounds__(256, 2)
gemm_f16(const __half* __restrict__ A16, const __half* __restrict__ B16,
         const float* __restrict__ bias,
         const float* __restrict__ gamma, const float* __restrict__ beta,
         __half* __restrict__ C16, int l, int M) {
    extern __shared__ char sb[];
    __half* sA = (__half*)(sb + SM_A);
    __half* sB = (__half*)(sb + SM_B);
    float* s_scale = (float*)(sb + SM_ST);
    float* s_shift = s_scale + 128;
    float* s_sum   = s_shift + 128;
    float* s_sq    = s_sum + 128;

    int tid = threadIdx.x;
    if (tid < 128) { s_sum[tid] = 0.0f; s_sq[tid] = 0.0f; }
    if (PRE_BN && tid < 128) {
        float inv = 1.0f / (float)M;
        float m = g_stats[l][0][tid] * inv;
        float v = g_stats[l][0][128 + tid] * inv - m * m;
        float s = __ldg(&gamma[tid]) * rsqrtf(v + BN_EPS);
        s_scale[tid] = s;
        s_shift[tid] = __ldg(&beta[tid]) - m * s;
    }

    // ---- stage B ([n][k] fp16, 8192 u32) ----
    const uint32_t* bsrc = (const uint32_t*)B16;
    #pragma unroll
    for (int it = 0; it < 32; ++it) {
        int i = tid + it * 256;
        int n = i >> 6, kp = i & 63;
        *(uint32_t*)&sB[n * LDT + kp * 2] = bsrc[i];
    }
    __syncthreads();   // scale/shift ready (PRE_BN)

    // ---- stage A (128 rows fp16; optional affine+relu) ----
    int row0 = blockIdx.x * 128;
    const uint2* A8 = (const uint2*)(A16 + (size_t)row0 * DH);
    #pragma unroll
    for (int it = 0; it < 16; ++it) {
        int idx = tid + it * 256;            // 4096 uint2
        int r = idx >> 5, c4 = (idx & 31) * 4;
        uint2 u = make_uint2(0u, 0u);
        if (row0 + r < M) u = A8[idx];
        if (PRE_BN) {
            float2 a = __half22float2(*(__half2*)&u.x);
            float2 b = __half22float2(*(__half2*)&u.y);
            a.x = fmaxf(fmaf(a.x, s_scale[c4 + 0], s_shift[c4 + 0]), 0.0f);
            a.y = fmaxf(fmaf(a.y, s_scale[c4 + 1], s_shift[c4 + 1]), 0.0f);
            b.x = fmaxf(fmaf(b.x, s_scale[c4 + 2], s_shift[c4 + 2]), 0.0f);
            b.y = fmaxf(fmaf(b.y, s_scale[c4 + 3], s_shift[c4 + 3]), 0.0f);
            __half2 ha = __floats2half2_rn(a.x, a.y);
            __half2 hb = __floats2half2_rn(b.x, b.y);
            u.x = *(uint32_t*)&ha; u.y = *(uint32_t*)&hb;
        }
        *(uint2*)&sA[r * LDT + c4] = u;
    }
    __syncthreads();

    // ---- warp tiling: 8 warps = 4(m) x 2(n), each 32(m) x 64(n) ----
    int w = tid >> 5, lane = tid & 31;
    int mw = (w >> 1) * 32, nw = (w & 1) * 64;
    uint32_t base = smem_u32(sb);
    uint32_t ab = base + ((mw + (lane & 15)) * LDT + ((lane >> 4) * 8)) * 2;
    uint32_t bb = base + SM_B +
                  ((nw + (lane & 7) + ((lane >> 4) << 3)) * LDT
                   + (((lane >> 3) & 1) * 8)) * 2;

    float acc[2][8][4];
    #pragma unroll
    for (int i = 0; i < 2; ++i)
        #pragma unroll
        for (int j = 0; j < 8; ++j)
            #pragma unroll
            for (int k = 0; k < 4; ++k) acc[i][j][k] = 0.0f;

    #pragma unroll
    for (int ks = 0; ks < 8; ++ks) {
        uint32_t a0[4], a1[4], b0[4], b1[4], b2[4], b3[4];
        ldx4(a0, ab + ks * 32);
        ldx4(a1, ab + 16 * LDT * 2 + ks * 32);
        ldx4(b0, bb + ks * 32);
        ldx4(b1, bb + 16 * LDT * 2 + ks * 32);
        ldx4(b2, bb + 32 * LDT * 2 + ks * 32);
        ldx4(b3, bb + 48 * LDT * 2 + ks * 32);
        #pragma unroll
        for (int mf = 0; mf < 2; ++mf) {
            uint32_t* a = mf ? a1 : a0;
            mma16816(acc[mf][0], a[0], a[1], a[2], a[3], b0[0], b0[1]);
            mma16816(acc[mf][1], a[0], a[1], a[2], a[3], b0[2], b0[3]);
            mma16816(acc[mf][2], a[0], a[1], a[2], a[3], b1[0], b1[1]);
            mma16816(acc[mf][3], a[0], a[1], a[2], a[3], b1[2], b1[3]);
            mma16816(acc[mf][4], a[0], a[1], a[2], a[3], b2[0], b2[1]);
            mma16816(acc[mf][5], a[0], a[1], a[2], a[3], b2[2], b2[3]);
            mma16816(acc[mf][6], a[0], a[1], a[2], a[3], b3[0], b3[1]);
            mma16816(acc[mf][7], a[0], a[1], a[2], a[3], b3[2], b3[3]);
        }
    }

    // ---- epilogue: bias, fp16 store, column stats (fp32, pre-rounding) ----
    #pragma unroll
    for (int nf = 0; nf < 8; ++nf) {
        int col = nw + nf * 8 + (lane & 3) * 2;
        float bx = __ldg(&bias[col]), by = __ldg(&bias[col + 1]);
        float cs0 = 0.f, cs1 = 0.f, cq0 = 0.f, cq1 = 0.f;
        #pragma unroll
        for (int mf = 0; mf < 2; ++mf) {
            int r0 = row0 + mw + mf * 16 + (lane >> 2);
            float v0 = acc[mf][nf][0] + bx, v1 = acc[mf][nf][1] + by;
            float v2 = acc[mf][nf][2] + bx, v3 = acc[mf][nf][3] + by;
            if (r0 < M) {
                __half2 h = __floats2half2_rn(v0, v1);
                *(uint32_t*)&C16[(size_t)r0 * DH + col] = *(uint32_t*)&h;
                cs0 += v0; cs1 += v1; cq0 += v0 * v0; cq1 += v1 * v1;
            }
            if (r0 + 8 < M) {
                __half2 h = __floats2half2_rn(v2, v3);
                *(uint32_t*)&C16[(size_t)(r0 + 8) * DH + col] = *(uint32_t*)&h;
                cs0 += v2; cs1 += v3; cq0 += v2 * v2; cq1 += v3 * v3;
            }
        }
        atomicAdd(&s_sum[col], cs0);
        atomicAdd(&s_sum[col + 1], cs1);
        atomicAdd(&s_sq[col], cq0);
        atomicAdd(&s_sq[col + 1], cq1);
    }
    __syncthreads();
    const int stage = PRE_BN ? 1 : 0;
    if (tid < 128) {
        atomicAdd(&g_stats[l][stage][tid], s_sum[tid]);
        atomicAdd(&g_stats[l][stage][128 + tid], s_sq[tid]);
    }
}

// ---------------- per-graph pooling for ONE rep (affine+ReLU on fly) ---
__global__ void pool_kernel(int lp, const float* __restrict__ go,
                            const float* __restrict__ bo, int M) {
    int g = blockIdx.x, c = threadIdx.x;   // 128 threads
    int s = g_gstart[g], e = g_gstart[g + 1];
    float acc = 0.0f;
    if (lp == 0) {
        const __half* h = g_x16;
        for (int r = s; r < e; ++r)
            acc += __half2float(__ldg(&h[(size_t)r * DH + c]));
    } else {
        int l = lp - 1;
        const __half* z = &g_z16[l][0];
        float inv = 1.0f / (float)M;
        float m = g_stats[l][1][c] * inv;
        float v = g_stats[l][1][128 + c] * inv - m * m;
        float scl = __ldg(&go[l * DH + c]) * rsqrtf(v + BN_EPS);
        float shf = __ldg(&bo[l * DH + c]) - m * scl;
        for (int r = s; r < e; ++r)
            acc += fmaxf(fmaf(__half2float(__ldg(&z[(size_t)r * DH + c])),
                              scl, shf), 0.0f);
    }
    g_ph[lp][g * DH + c] = acc;
}

// ---------------- final score: 512 x 64 --------------------------------
__global__ void score_kernel(const float* __restrict__ Wp,
                             const float* __restrict__ bp,
                             float* __restrict__ out) {
    int g = blockIdx.x;
    __shared__ float sph[NL * DH];
    for (int i = threadIdx.x; i < NL * DH; i += blockDim.x) {
        int l = i / DH, c = i % DH;
        sph[i] = g_ph[l][g * DH + c];
    }
    __syncthreads();
    int o = threadIdx.x;  // 64 threads
    float acc = 0.0f;
    for (int l = 0; l < NL; ++l) {
        acc += __ldg(&bp[l * OO + o]);
        const float* Wl = Wp + (size_t)l * DH * OO;
        #pragma unroll 4
        for (int c = 0; c < DH; ++c)
            acc = fmaf(sph[l * DH + c], __ldg(&Wl[c * OO + o]), acc);
    }
    out[g * OO + o] = acc;
}

// ---------------- launcher ---------------------------------------------
extern "C" void kernel_launch(void* const* d_in, const int* in_sizes, int n_in,
                              void* d_out, int out_size) {
    const float* x   = (const float*)d_in[0];
    const int*   src = (const int*)d_in[1];
    const int*   dst = (const int*)d_in[2];
    const int*   gid = (const int*)d_in[3];
    const float* eps = (const float*)d_in[5];
    const float* W1  = (const float*)d_in[6];
    const float* b1  = (const float*)d_in[7];
    const float* gm  = (const float*)d_in[8];
    const float* bm  = (const float*)d_in[9];
    const float* W2  = (const float*)d_in[10];
    const float* b2  = (const float*)d_in[11];
    const float* go  = (const float*)d_in[12];
    const float* bo  = (const float*)d_in[13];
    const float* Wp  = (const float*)d_in[14];
    const float* bp  = (const float*)d_in[15];
    float* out = (float*)d_out;

    int N = in_sizes[0] / DH;   // 100000
    int E = in_sizes[1];        // 1600000

    __half *x16, *z16, *pooled16, *y16, *w16;
    cudaGetSymbolAddress((void**)&x16, g_x16);
    cudaGetSymbolAddress((void**)&z16, g_z16);
    cudaGetSymbolAddress((void**)&pooled16, g_pooled16);
    cudaGetSymbolAddress((void**)&y16, g_y16);
    cudaGetSymbolAddress((void**)&w16, g_w16);

    static cudaStream_t s1 = nullptr, s2 = nullptr;
    static cudaEvent_t evFork = nullptr, evSide = nullptr,
                       evZ = nullptr, evP = nullptr;
    if (!s1) {
        cudaStreamCreateWithFlags(&s1, cudaStreamNonBlocking);
        cudaStreamCreateWithFlags(&s2, cudaStreamNonBlocking);
        cudaEventCreateWithFlags(&evFork, cudaEventDisableTiming);
        cudaEventCreateWithFlags(&evSide, cudaEventDisableTiming);
        cudaEventCreateWithFlags(&evZ, cudaEventDisableTiming);
        cudaEventCreateWithFlags(&evP, cudaEventDisableTiming);
        cudaFuncSetAttribute(gemm_f16<false>,
                             cudaFuncAttributeMaxDynamicSharedMemorySize, SMEM_BYTES);
        cudaFuncSetAttribute(gemm_f16<true>,
                             cudaFuncAttributeMaxDynamicSharedMemorySize, SMEM_BYTES);
    }

    int nb = (N + 1023) / 1024;
    int elemGrid = (N * 32 + 255) / 256;
    int gemmGrid = (N + 127) / 128;
    int aggGrid  = (N * 32 + 255) / 256;  // warp per node

    // ---- fork side stream for independent prep work ----
    cudaEventRecord(evFork, 0);
    cudaStreamWaitEvent(s1, evFork, 0);
    xconv_kernel<<<elemGrid, 256, 0, s1>>>(x, N);
    wconv_kernel<<<(8 * DH * DH + 255) / 256, 256, 0, s1>>>(W1, W2);
    gbounds_kernel<<<(N + 1 + 255) / 256, 256, 0, s1>>>(gid, N);
    cudaEventRecord(evSide, s1);

    // ---- main: CSR build ----
    zero_kernel<<<(N + 255) / 256, 256>>>(N);
    hist_kernel<<<(E + 255) / 256, 256>>>(dst, E);
    scan1_kernel<<<nb, 1024>>>(N);
    scan2_kernel<<<1, 128>>>(nb);
    scan3_kernel<<<(N + 255) / 256, 256>>>(N);
    scatter_kernel<<<(E + 255) / 256, 256>>>(src, dst, E);
    cudaStreamWaitEvent(0, evSide, 0);

    // ---- pool stream: rep 0 needs x16 + gbounds ----
    cudaStreamWaitEvent(s2, evSide, 0);
    pool_kernel<<<NG, DH, 0, s2>>>(0, go, bo, N);

    // ---- layer loop on main; pools overlap on s2 ----
    for (int l = 0; l < NLG; ++l) {
        __half* zl = z16 + (size_t)l * (size_t)NNODES * DH;
        if (l == 0) {
            agg_kernel<true><<<aggGrid, 256>>>(x16, nullptr, nullptr, eps, l, N);
        } else {
            const __half* zp = z16 + (size_t)(l - 1) * (size_t)NNODES * DH;
            agg_kernel<false><<<aggGrid, 256>>>(zp, go + (l - 1) * DH,
                                                bo + (l - 1) * DH, eps, l, N);
        }
        gemm_f16<false><<<gemmGrid, 256, SMEM_BYTES>>>(
            pooled16, w16 + (size_t)l * DH * DH,
            b1 + l * DH, nullptr, nullptr, y16, l, N);
        gemm_f16<true><<<gemmGrid, 256, SMEM_BYTES>>>(
            y16, w16 + (size_t)(4 + l) * DH * DH,
            b2 + l * DH, gm + l * DH, bm + l * DH, zl, l, N);
        cudaEventRecord(evZ, 0);
        cudaStreamWaitEvent(s2, evZ, 0);
        pool_kernel<<<NG, DH, 0, s2>>>(l + 1, go, bo, N);
    }

    // ---- join pools, final score ----
    cudaEventRecord(evP, s2);
    cudaStreamWaitEvent(0, evP, 0);
    score_kernel<<<NG, 64>>>(Wp, bp, out);
}